// round 6
// baseline (speedup 1.0000x reference)
#include <cuda_runtime.h>

// ---------------- problem constants (shapes fixed by the dataset) ----------
#define NMAX   50000
#define EMAX   800000
#define HDIM   128
#define CDIM   256      // 2*H
#define GNUM   128

// ---------------- scratch (static device globals; no runtime allocation) --
__device__ __align__(16) float g_h     [NMAX * HDIM];     // node embeddings      [N,128]
__device__ __align__(16) float g_cf    [NMAX * HDIM];     // hyperedge embeddings [NHE,128]
__device__ __align__(16) float g_zA    [NMAX * CDIM];     // h @ (Wa+Wc)          [N,256]
__device__ __align__(16) float g_zB    [NMAX * CDIM];     // cf @ Wb + lin_b      [NHE,256]
__device__ __align__(16) float g_num   [NMAX * HDIM];     // softmax numerator    [N,128]
__device__ __align__(16) float g_den   [NMAX * HDIM];     // softmax denominator  [N,128]
__device__ __align__(16) float g_stats1[2 * CDIM];        // BN1 sum / sumsq
__device__ __align__(16) float g_scale1[CDIM];
__device__ __align__(16) float g_shift1[CDIM];
__device__ __align__(16) float g_stats2[2 * HDIM];        // BN2 sum / sumsq
__device__ __align__(16) float g_scale2[HDIM];
__device__ __align__(16) float g_shift2[HDIM];
__device__ __align__(16) float g_pooled[GNUM * HDIM];
__device__ __align__(16) float g_counts[GNUM];

// ---------------- helpers --------------------------------------------------
static __device__ __forceinline__ float softplusf(float x) {
    // matches jax.nn.softplus = log1p(exp(x)) computed stably
    return fmaxf(x, 0.f) + log1pf(__expf(-fabsf(x)));
}
static __device__ __forceinline__ float sigmoidf(float x) {
    return 1.f / (1.f + __expf(-x));
}
static __device__ __forceinline__ void red_add_v4(float* p, float a, float b, float c, float d) {
    asm volatile("red.global.add.v4.f32 [%0], {%1, %2, %3, %4};"
                 :: "l"(p), "f"(a), "f"(b), "f"(c), "f"(d) : "memory");
}

// ---------------- generic fp32 GEMM: C[M,N] = A[M,K] @ (B1+B2)[K,N] + bias -
// BM=128, BN=128, BK=16, 256 threads, 8x8 per-thread microtile.
__global__ void __launch_bounds__(256) sgemm(
    const float* __restrict__ A, const float* __restrict__ B1,
    const float* __restrict__ B2, const float* __restrict__ bias,
    float* __restrict__ C, int M, int N, int K)
{
    __shared__ float As[16][128];
    __shared__ float Bs[16][128];

    const int tid = threadIdx.x;
    const int m0  = blockIdx.x * 128;
    const int n0  = blockIdx.y * 128;
    const int tm  = tid >> 4;          // 0..15 (row group)
    const int tn  = tid & 15;          // 0..15 (col group)

    // load mapping
    const int lm  = tid >> 1;          // A tile row 0..127
    const int lk  = (tid & 1) * 8;     // A tile k offset 0 or 8
    const int lkB = tid >> 4;          // B tile k row 0..15
    const int lnB = (tid & 15) * 8;    // B tile col offset

    float acc[8][8];
    #pragma unroll
    for (int i = 0; i < 8; i++)
        #pragma unroll
        for (int j = 0; j < 8; j++) acc[i][j] = 0.f;

    for (int k0 = 0; k0 < K; k0 += 16) {
        // ---- load A tile (transposed into As[k][m]) ----
        {
            const int row = m0 + lm;
            if (row < M && (k0 + 16 <= K)) {
                const float* ap = A + (long long)row * K + k0 + lk;
                float4 v0 = *(const float4*)(ap);
                float4 v1 = *(const float4*)(ap + 4);
                As[lk + 0][lm] = v0.x; As[lk + 1][lm] = v0.y;
                As[lk + 2][lm] = v0.z; As[lk + 3][lm] = v0.w;
                As[lk + 4][lm] = v1.x; As[lk + 5][lm] = v1.y;
                As[lk + 6][lm] = v1.z; As[lk + 7][lm] = v1.w;
            } else {
                #pragma unroll
                for (int i = 0; i < 8; i++) {
                    int kk = k0 + lk + i;
                    As[lk + i][lm] = (row < M && kk < K)
                                   ? A[(long long)row * K + kk] : 0.f;
                }
            }
        }
        // ---- load B tile ----
        {
            const int kk = k0 + lkB;
            float4 v0 = {0,0,0,0}, v1 = {0,0,0,0};
            if (kk < K) {
                const float* bp = B1 + (long long)kk * N + n0 + lnB;
                v0 = *(const float4*)bp;
                v1 = *(const float4*)(bp + 4);
                if (B2) {
                    const float* bp2 = B2 + (long long)kk * N + n0 + lnB;
                    float4 w0 = *(const float4*)bp2;
                    float4 w1 = *(const float4*)(bp2 + 4);
                    v0.x += w0.x; v0.y += w0.y; v0.z += w0.z; v0.w += w0.w;
                    v1.x += w1.x; v1.y += w1.y; v1.z += w1.z; v1.w += w1.w;
                }
            }
            *(float4*)&Bs[lkB][lnB]     = v0;
            *(float4*)&Bs[lkB][lnB + 4] = v1;
        }
        __syncthreads();

        #pragma unroll
        for (int kk = 0; kk < 16; kk++) {
            float a[8], b[8];
            *(float4*)(a)     = *(const float4*)&As[kk][tm * 8];
            *(float4*)(a + 4) = *(const float4*)&As[kk][tm * 8 + 4];
            *(float4*)(b)     = *(const float4*)&Bs[kk][tn * 8];
            *(float4*)(b + 4) = *(const float4*)&Bs[kk][tn * 8 + 4];
            #pragma unroll
            for (int i = 0; i < 8; i++)
                #pragma unroll
                for (int j = 0; j < 8; j++)
                    acc[i][j] += a[i] * b[j];
        }
        __syncthreads();
    }

    // ---- epilogue ----
    float bs[8];
    #pragma unroll
    for (int j = 0; j < 8; j++)
        bs[j] = bias ? bias[n0 + tn * 8 + j] : 0.f;

    #pragma unroll
    for (int i = 0; i < 8; i++) {
        const int row = m0 + tm * 8 + i;
        if (row < M) {
            float* cp = C + (long long)row * N + n0 + tn * 8;
            float4 o0 = {acc[i][0] + bs[0], acc[i][1] + bs[1],
                         acc[i][2] + bs[2], acc[i][3] + bs[3]};
            float4 o1 = {acc[i][4] + bs[4], acc[i][5] + bs[5],
                         acc[i][6] + bs[6], acc[i][7] + bs[7]};
            *(float4*)(cp)     = o0;
            *(float4*)(cp + 4) = o1;
        }
    }
}

// ---------------- edge pass 1: BN1 statistics over z = zA[i0]+zB[i1] -------
// warp per edge (grid-stride); lane l holds channels 4l..4l+3 and 128+4l..
__global__ void __launch_bounds__(256) edge_stats(
    const int* __restrict__ idx0, const int* __restrict__ idx1, int E)
{
    __shared__ float ss[512];
    const int tid = threadIdx.x;
    for (int i = tid; i < 512; i += 256) ss[i] = 0.f;
    __syncthreads();

    const int lane = tid & 31;
    int warp = blockIdx.x * 8 + (tid >> 5);
    const int nW = gridDim.x * 8;
    const float4* zA4 = (const float4*)g_zA;
    const float4* zB4 = (const float4*)g_zB;

    float s0x=0,s0y=0,s0z=0,s0w=0, s1x=0,s1y=0,s1z=0,s1w=0;
    float q0x=0,q0y=0,q0z=0,q0w=0, q1x=0,q1y=0,q1z=0,q1w=0;

    for (int e = warp; e < E; e += nW) {
        const int i0 = idx0[e];
        const int i1 = idx1[e];
        float4 a0 = zA4[(size_t)i0 * 64 + lane];
        float4 a1 = zA4[(size_t)i0 * 64 + 32 + lane];
        float4 b0 = zB4[(size_t)i1 * 64 + lane];
        float4 b1 = zB4[(size_t)i1 * 64 + 32 + lane];
        float z0x=a0.x+b0.x, z0y=a0.y+b0.y, z0z=a0.z+b0.z, z0w=a0.w+b0.w;
        float z1x=a1.x+b1.x, z1y=a1.y+b1.y, z1z=a1.z+b1.z, z1w=a1.w+b1.w;
        s0x+=z0x; s0y+=z0y; s0z+=z0z; s0w+=z0w;
        s1x+=z1x; s1y+=z1y; s1z+=z1z; s1w+=z1w;
        q0x+=z0x*z0x; q0y+=z0y*z0y; q0z+=z0z*z0z; q0w+=z0w*z0w;
        q1x+=z1x*z1x; q1y+=z1y*z1y; q1z+=z1z*z1z; q1w+=z1w*z1w;
    }

    const int c = lane * 4;
    atomicAdd(&ss[c + 0], s0x); atomicAdd(&ss[c + 1], s0y);
    atomicAdd(&ss[c + 2], s0z); atomicAdd(&ss[c + 3], s0w);
    atomicAdd(&ss[128 + c + 0], s1x); atomicAdd(&ss[128 + c + 1], s1y);
    atomicAdd(&ss[128 + c + 2], s1z); atomicAdd(&ss[128 + c + 3], s1w);
    atomicAdd(&ss[256 + c + 0], q0x); atomicAdd(&ss[256 + c + 1], q0y);
    atomicAdd(&ss[256 + c + 2], q0z); atomicAdd(&ss[256 + c + 3], q0w);
    atomicAdd(&ss[384 + c + 0], q1x); atomicAdd(&ss[384 + c + 1], q1y);
    atomicAdd(&ss[384 + c + 2], q1z); atomicAdd(&ss[384 + c + 3], q1w);
    __syncthreads();
    for (int i = tid; i < 512; i += 256) atomicAdd(&g_stats1[i], ss[i]);
}

// ---------------- BN finalize: scale/shift from sum/sumsq ------------------
__global__ void bn_finalize(const float* __restrict__ stats,
                            const float* __restrict__ gma,
                            const float* __restrict__ bta,
                            float inv, int C,
                            float* __restrict__ scale, float* __restrict__ shift)
{
    const int c = blockIdx.x * blockDim.x + threadIdx.x;
    if (c < C) {
        float mean = stats[c] * inv;
        float var  = stats[C + c] * inv - mean * mean;
        float s    = gma[c] * rsqrtf(var + 1e-5f);
        scale[c] = s;
        shift[c] = bta[c] - mean * s;
    }
}

// ---------------- edge pass 2: message + softmax-aggregation ---------------
__global__ void __launch_bounds__(256) edge_msg(
    const int* __restrict__ idx0, const int* __restrict__ idx1,
    const float* __restrict__ aggr_t, int E)
{
    const int tid  = threadIdx.x;
    const int lane = tid & 31;
    const float4 sf = *(const float4*)&g_scale1[4 * lane];
    const float4 tf = *(const float4*)&g_shift1[4 * lane];
    const float4 sc = *(const float4*)&g_scale1[128 + 4 * lane];
    const float4 tc = *(const float4*)&g_shift1[128 + 4 * lane];
    const float  T  = *aggr_t;

    int warp = blockIdx.x * 8 + (tid >> 5);
    const int nW = gridDim.x * 8;
    const float4* zA4 = (const float4*)g_zA;
    const float4* zB4 = (const float4*)g_zB;

    for (int e = warp; e < E; e += nW) {
        const int i0 = idx0[e];
        const int i1 = idx1[e];
        float4 a0 = zA4[(size_t)i0 * 64 + lane];
        float4 a1 = zA4[(size_t)i0 * 64 + 32 + lane];
        float4 b0 = zB4[(size_t)i1 * 64 + lane];
        float4 b1 = zB4[(size_t)i1 * 64 + 32 + lane];

        float zfx = (a0.x + b0.x) * sf.x + tf.x;
        float zfy = (a0.y + b0.y) * sf.y + tf.y;
        float zfz = (a0.z + b0.z) * sf.z + tf.z;
        float zfw = (a0.w + b0.w) * sf.w + tf.w;
        float zcx = (a1.x + b1.x) * sc.x + tc.x;
        float zcy = (a1.y + b1.y) * sc.y + tc.y;
        float zcz = (a1.z + b1.z) * sc.z + tc.z;
        float zcw = (a1.w + b1.w) * sc.w + tc.w;

        float mx = sigmoidf(zfx) * softplusf(zcx);
        float my = sigmoidf(zfy) * softplusf(zcy);
        float mz = sigmoidf(zfz) * softplusf(zcz);
        float mw = sigmoidf(zfw) * softplusf(zcw);

        float ex = __expf(T * mx);
        float ey = __expf(T * my);
        float ez = __expf(T * mz);
        float ew = __expf(T * mw);

        float* dp = g_den + (size_t)i0 * 128 + 4 * lane;
        float* np = g_num + (size_t)i0 * 128 + 4 * lane;
        red_add_v4(dp, ex, ey, ez, ew);
        red_add_v4(np, mx * ex, my * ey, mz * ez, mw * ew);
    }
}

// ---------------- node pass A: out = num/den, BN2 stats, graph counts ------
__global__ void __launch_bounds__(256) node_stats(
    const int* __restrict__ batch, int N)
{
    __shared__ float ss[256];
    const int tid = threadIdx.x;
    ss[tid] = 0.f;
    __syncthreads();

    const int gid = blockIdx.x * 256 + tid;
    const int n = gid >> 5;
    const int g = gid & 31;
    if (n < N) {
        const float4* num4 = (const float4*)g_num;
        const float4* den4 = (const float4*)g_den;
        float4 nm = num4[(size_t)n * 32 + g];
        float4 dn = den4[(size_t)n * 32 + g];
        float ox = nm.x / (dn.x + 1e-16f);
        float oy = nm.y / (dn.y + 1e-16f);
        float oz = nm.z / (dn.z + 1e-16f);
        float ow = nm.w / (dn.w + 1e-16f);
        const int c = 4 * g;
        atomicAdd(&ss[c + 0], ox); atomicAdd(&ss[c + 1], oy);
        atomicAdd(&ss[c + 2], oz); atomicAdd(&ss[c + 3], ow);
        atomicAdd(&ss[128 + c + 0], ox * ox); atomicAdd(&ss[128 + c + 1], oy * oy);
        atomicAdd(&ss[128 + c + 2], oz * oz); atomicAdd(&ss[128 + c + 3], ow * ow);
        if (g == 0) atomicAdd(&g_counts[batch[n]], 1.f);
    }
    __syncthreads();
    atomicAdd(&g_stats2[tid], ss[tid]);
}

// ---------------- node pass B: h' = softplus(BN2(out)+h); pool by graph ----
__global__ void __launch_bounds__(256) node_final(
    const int* __restrict__ batch, int N)
{
    const int gid = blockIdx.x * 256 + threadIdx.x;
    const int n = gid >> 5;
    const int g = gid & 31;
    if (n >= N) return;

    const float4* num4 = (const float4*)g_num;
    const float4* den4 = (const float4*)g_den;
    float4 nm = num4[(size_t)n * 32 + g];
    float4 dn = den4[(size_t)n * 32 + g];
    float4 s2 = *(const float4*)&g_scale2[4 * g];
    float4 t2 = *(const float4*)&g_shift2[4 * g];
    float4 hv = ((const float4*)g_h)[(size_t)n * 32 + g];

    float vx = softplusf((nm.x / (dn.x + 1e-16f)) * s2.x + t2.x + hv.x);
    float vy = softplusf((nm.y / (dn.y + 1e-16f)) * s2.y + t2.y + hv.y);
    float vz = softplusf((nm.z / (dn.z + 1e-16f)) * s2.z + t2.z + hv.z);
    float vw = softplusf((nm.w / (dn.w + 1e-16f)) * s2.w + t2.w + hv.w);

    const int b = batch[n];
    red_add_v4(&g_pooled[(size_t)b * 128 + 4 * g], vx, vy, vz, vw);
}

// ---------------- head: mean pool -> softplus(MLP) -> linear ---------------
__global__ void __launch_bounds__(256) head(
    const float* __restrict__ l1_w, const float* __restrict__ l1_b,
    const float* __restrict__ out_w, const float* __restrict__ out_b,
    float* __restrict__ out)
{
    __shared__ float p[128];
    __shared__ float red[256];
    const int g = blockIdx.x;
    const int tid = threadIdx.x;
    if (tid < 128)
        p[tid] = g_pooled[g * 128 + tid] / fmaxf(g_counts[g], 1.f);
    __syncthreads();

    float acc = l1_b[tid];
    #pragma unroll 8
    for (int k = 0; k < 128; k++)
        acc += p[k] * l1_w[k * 256 + tid];
    red[tid] = softplusf(acc) * out_w[tid];
    __syncthreads();
    for (int s = 128; s > 0; s >>= 1) {
        if (tid < s) red[tid] += red[tid + s];
        __syncthreads();
    }
    if (tid == 0) out[g] = red[0] + out_b[0];
}

// ---------------- launch ---------------------------------------------------
extern "C" void kernel_launch(void* const* d_in, const int* in_sizes, int n_in,
                              void* d_out, int out_size)
{
    const float* x        = (const float*)d_in[0];
    const float* hedge    = (const float*)d_in[1];
    const int*   rel      = (const int*)d_in[2];      // int32 (JAX x64 disabled)
    const int*   batch    = (const int*)d_in[3];      // int32
    // d_in[4] = num_nodes (unused; derived from sizes)
    const float* embed_w  = (const float*)d_in[5];
    const float* embed_b  = (const float*)d_in[6];
    const float* bembed_w = (const float*)d_in[7];
    const float* bembed_b = (const float*)d_in[8];
    const float* lin_w    = (const float*)d_in[9];
    const float* lin_b    = (const float*)d_in[10];
    const float* bn1_g    = (const float*)d_in[11];
    const float* bn1_b    = (const float*)d_in[12];
    const float* bn2_g    = (const float*)d_in[13];
    const float* bn2_b    = (const float*)d_in[14];
    const float* aggr_t   = (const float*)d_in[15];
    const float* l1_w     = (const float*)d_in[16];
    const float* l1_b     = (const float*)d_in[17];
    const float* out_w    = (const float*)d_in[18];
    const float* out_b    = (const float*)d_in[19];

    const int N   = in_sizes[0] / 92;
    const int NHE = in_sizes[1] / 40;
    const int E   = in_sizes[2] / 3;
    const int* idx0 = rel;
    const int* idx1 = rel + E;

    void *p_h, *p_cf, *p_zA, *p_zB, *p_num, *p_den;
    void *p_st1, *p_sc1, *p_sh1, *p_st2, *p_sc2, *p_sh2, *p_pool, *p_cnt;
    cudaGetSymbolAddress(&p_h,   g_h);
    cudaGetSymbolAddress(&p_cf,  g_cf);
    cudaGetSymbolAddress(&p_zA,  g_zA);
    cudaGetSymbolAddress(&p_zB,  g_zB);
    cudaGetSymbolAddress(&p_num, g_num);
    cudaGetSymbolAddress(&p_den, g_den);
    cudaGetSymbolAddress(&p_st1, g_stats1);
    cudaGetSymbolAddress(&p_sc1, g_scale1);
    cudaGetSymbolAddress(&p_sh1, g_shift1);
    cudaGetSymbolAddress(&p_st2, g_stats2);
    cudaGetSymbolAddress(&p_sc2, g_scale2);
    cudaGetSymbolAddress(&p_sh2, g_shift2);
    cudaGetSymbolAddress(&p_pool, g_pooled);
    cudaGetSymbolAddress(&p_cnt,  g_counts);

    cudaMemsetAsync(p_num, 0, (size_t)N * HDIM * sizeof(float));
    cudaMemsetAsync(p_den, 0, (size_t)N * HDIM * sizeof(float));
    cudaMemsetAsync(p_st1, 0, 2 * CDIM * sizeof(float));
    cudaMemsetAsync(p_st2, 0, 2 * HDIM * sizeof(float));
    cudaMemsetAsync(p_pool, 0, GNUM * HDIM * sizeof(float));
    cudaMemsetAsync(p_cnt,  0, GNUM * sizeof(float));

    const dim3 t256(256);
    const int mbN   = (N   + 127) / 128;
    const int mbNHE = (NHE + 127) / 128;

    // embeddings
    sgemm<<<dim3(mbN, 1),   t256>>>(x,     embed_w,  nullptr, embed_b,  (float*)p_h,  N,   128, 92);
    sgemm<<<dim3(mbNHE, 1), t256>>>(hedge, bembed_w, nullptr, bembed_b, (float*)p_cf, NHE, 128, 40);
    // factored edge-linear: zA = h@(Wa+Wc), zB = cf@Wb + lin_b
    sgemm<<<dim3(mbN, 2),   t256>>>((float*)p_h,  lin_w,             lin_w + 256 * 256, nullptr, (float*)p_zA, N,   256, 128);
    sgemm<<<dim3(mbNHE, 2), t256>>>((float*)p_cf, lin_w + 128 * 256, nullptr,           lin_b,   (float*)p_zB, NHE, 256, 128);

    edge_stats<<<1184, t256>>>(idx0, idx1, E);
    bn_finalize<<<1, 256>>>((float*)p_st1, bn1_g, bn1_b, 1.0f / (float)E, 256,
                            (float*)p_sc1, (float*)p_sh1);
    edge_msg<<<1184, t256>>>(idx0, idx1, aggr_t, E);

    const int nodeBlocks = (N * 32 + 255) / 256;
    node_stats<<<nodeBlocks, t256>>>(batch, N);
    bn_finalize<<<1, 128>>>((float*)p_st2, bn2_g, bn2_b, 1.0f / (float)N, 128,
                            (float*)p_sc2, (float*)p_sh2);
    node_final<<<nodeBlocks, t256>>>(batch, N);

    head<<<GNUM, t256>>>(l1_w, l1_b, out_w, out_b, (float*)d_out);
}

// round 7
// speedup vs baseline: 1.0263x; 1.0263x over previous
#include <cuda_runtime.h>

// ---------------- problem constants (shapes fixed by the dataset) ----------
#define NMAX   50000
#define EMAX   800000
#define HDIM   128
#define CDIM   256      // 2*H
#define GNUM   128

// ---------------- scratch (static device globals; no runtime allocation) --
__device__ __align__(16) float g_h     [NMAX * HDIM];     // node embeddings      [N,128]
__device__ __align__(16) float g_cf    [NMAX * HDIM];     // hyperedge embeddings [NHE,128]
__device__ __align__(16) float g_zA    [NMAX * CDIM];     // h @ (Wa+Wc)          [N,256]
__device__ __align__(16) float g_zB    [NMAX * CDIM];     // cf @ Wb + lin_b      [NHE,256]
__device__ __align__(16) float g_out   [NMAX * HDIM];     // aggregated msgs      [N,128]
__device__ __align__(16) float g_stats1[2 * CDIM];        // BN1 sum / sumsq
__device__ __align__(16) float g_scale1[CDIM];
__device__ __align__(16) float g_shift1[CDIM];
__device__ __align__(16) float g_stats2[2 * HDIM];        // BN2 sum / sumsq
__device__ __align__(16) float g_scale2[HDIM];
__device__ __align__(16) float g_shift2[HDIM];
__device__ __align__(16) float g_pooled[GNUM * HDIM];
__device__ __align__(16) float g_counts[GNUM];
// CSR scratch
__device__ int g_cnt0  [NMAX];      // node in-degree (i0)
__device__ int g_cnt1  [NMAX];      // hyperedge degree (i1)
__device__ int g_base  [NMAX];      // exclusive prefix of cnt0
__device__ int g_cursor[NMAX];      // scatter cursors
__device__ int g_ei1   [EMAX];      // i1 of edges, grouped by i0

// ---------------- helpers --------------------------------------------------
static __device__ __forceinline__ float softplusf(float x) {
    return fmaxf(x, 0.f) + log1pf(__expf(-fabsf(x)));
}
static __device__ __forceinline__ float sigmoidf(float x) {
    return 1.f / (1.f + __expf(-x));
}
static __device__ __forceinline__ void red_add_v4(float* p, float a, float b, float c, float d) {
    asm volatile("red.global.add.v4.f32 [%0], {%1, %2, %3, %4};"
                 :: "l"(p), "f"(a), "f"(b), "f"(c), "f"(d) : "memory");
}
static __device__ __forceinline__ float4 f4add(float4 a, float4 b) {
    return make_float4(a.x + b.x, a.y + b.y, a.z + b.z, a.w + b.w);
}

// ---------------- generic fp32 GEMM: C[M,N] = A[M,K] @ (B1+B2)[K,N] + bias -
__global__ void __launch_bounds__(256) sgemm(
    const float* __restrict__ A, const float* __restrict__ B1,
    const float* __restrict__ B2, const float* __restrict__ bias,
    float* __restrict__ C, int M, int N, int K)
{
    __shared__ float As[16][128];
    __shared__ float Bs[16][128];

    const int tid = threadIdx.x;
    const int m0  = blockIdx.x * 128;
    const int n0  = blockIdx.y * 128;
    const int tm  = tid >> 4;
    const int tn  = tid & 15;

    const int lm  = tid >> 1;
    const int lk  = (tid & 1) * 8;
    const int lkB = tid >> 4;
    const int lnB = (tid & 15) * 8;

    float acc[8][8];
    #pragma unroll
    for (int i = 0; i < 8; i++)
        #pragma unroll
        for (int j = 0; j < 8; j++) acc[i][j] = 0.f;

    for (int k0 = 0; k0 < K; k0 += 16) {
        {
            const int row = m0 + lm;
            if (row < M && (k0 + 16 <= K)) {
                const float* ap = A + (long long)row * K + k0 + lk;
                float4 v0 = *(const float4*)(ap);
                float4 v1 = *(const float4*)(ap + 4);
                As[lk + 0][lm] = v0.x; As[lk + 1][lm] = v0.y;
                As[lk + 2][lm] = v0.z; As[lk + 3][lm] = v0.w;
                As[lk + 4][lm] = v1.x; As[lk + 5][lm] = v1.y;
                As[lk + 6][lm] = v1.z; As[lk + 7][lm] = v1.w;
            } else {
                #pragma unroll
                for (int i = 0; i < 8; i++) {
                    int kk = k0 + lk + i;
                    As[lk + i][lm] = (row < M && kk < K)
                                   ? A[(long long)row * K + kk] : 0.f;
                }
            }
        }
        {
            const int kk = k0 + lkB;
            float4 v0 = {0,0,0,0}, v1 = {0,0,0,0};
            if (kk < K) {
                const float* bp = B1 + (long long)kk * N + n0 + lnB;
                v0 = *(const float4*)bp;
                v1 = *(const float4*)(bp + 4);
                if (B2) {
                    const float* bp2 = B2 + (long long)kk * N + n0 + lnB;
                    float4 w0 = *(const float4*)bp2;
                    float4 w1 = *(const float4*)(bp2 + 4);
                    v0.x += w0.x; v0.y += w0.y; v0.z += w0.z; v0.w += w0.w;
                    v1.x += w1.x; v1.y += w1.y; v1.z += w1.z; v1.w += w1.w;
                }
            }
            *(float4*)&Bs[lkB][lnB]     = v0;
            *(float4*)&Bs[lkB][lnB + 4] = v1;
        }
        __syncthreads();

        #pragma unroll
        for (int kk = 0; kk < 16; kk++) {
            float a[8], b[8];
            *(float4*)(a)     = *(const float4*)&As[kk][tm * 8];
            *(float4*)(a + 4) = *(const float4*)&As[kk][tm * 8 + 4];
            *(float4*)(b)     = *(const float4*)&Bs[kk][tn * 8];
            *(float4*)(b + 4) = *(const float4*)&Bs[kk][tn * 8 + 4];
            #pragma unroll
            for (int i = 0; i < 8; i++)
                #pragma unroll
                for (int j = 0; j < 8; j++)
                    acc[i][j] += a[i] * b[j];
        }
        __syncthreads();
    }

    float bs[8];
    #pragma unroll
    for (int j = 0; j < 8; j++)
        bs[j] = bias ? bias[n0 + tn * 8 + j] : 0.f;

    #pragma unroll
    for (int i = 0; i < 8; i++) {
        const int row = m0 + tm * 8 + i;
        if (row < M) {
            float* cp = C + (long long)row * N + n0 + tn * 8;
            float4 o0 = {acc[i][0] + bs[0], acc[i][1] + bs[1],
                         acc[i][2] + bs[2], acc[i][3] + bs[3]};
            float4 o1 = {acc[i][4] + bs[4], acc[i][5] + bs[5],
                         acc[i][6] + bs[6], acc[i][7] + bs[7]};
            *(float4*)(cp)     = o0;
            *(float4*)(cp + 4) = o1;
        }
    }
}

// ---------------- CSR build ------------------------------------------------
__global__ void __launch_bounds__(256) count_edges(
    const int* __restrict__ idx0, const int* __restrict__ idx1, int E)
{
    for (int e = blockIdx.x * 256 + threadIdx.x; e < E; e += gridDim.x * 256) {
        atomicAdd(&g_cnt0[idx0[e]], 1);
        atomicAdd(&g_cnt1[idx1[e]], 1);
    }
}

// single-block exclusive scan of g_cnt0 -> g_base (+ cursor copy)
__global__ void __launch_bounds__(1024) scan_counts(int N)
{
    __shared__ int sh[1024];
    const int tid   = threadIdx.x;
    const int chunk = (N + 1023) / 1024;
    const int start = tid * chunk;
    const int end   = min(start + chunk, N);

    int s = 0;
    for (int i = start; i < end; i++) s += g_cnt0[i];
    sh[tid] = s;
    __syncthreads();
    for (int off = 1; off < 1024; off <<= 1) {
        int v = (tid >= off) ? sh[tid - off] : 0;
        __syncthreads();
        sh[tid] += v;
        __syncthreads();
    }
    int run = sh[tid] - s;   // exclusive prefix of this thread's chunk
    for (int i = start; i < end; i++) {
        int c = g_cnt0[i];
        g_base[i]   = run;
        g_cursor[i] = run;
        run += c;
    }
}

__global__ void __launch_bounds__(256) scatter_edges(
    const int* __restrict__ idx0, const int* __restrict__ idx1, int E)
{
    for (int e = blockIdx.x * 256 + threadIdx.x; e < E; e += gridDim.x * 256) {
        int p = atomicAdd(&g_cursor[idx0[e]], 1);
        g_ei1[p] = idx1[e];
    }
}

// ---------------- BN1 stats, hyperedge side: cnt1*zB, cnt1*zB^2 ------------
__global__ void __launch_bounds__(256) hedge_stats(int NHE)
{
    __shared__ float ss[512];
    const int tid = threadIdx.x;
    for (int i = tid; i < 512; i += 256) ss[i] = 0.f;
    __syncthreads();

    const int gid = blockIdx.x * 256 + tid;
    const int m = gid >> 5;
    const int g = gid & 31;
    if (m < NHE) {
        const float c1 = (float)g_cnt1[m];
        if (c1 > 0.f) {
            const float4* zB4 = (const float4*)g_zB;
            float4 b0 = zB4[(size_t)m * 64 + g];
            float4 b1 = zB4[(size_t)m * 64 + 32 + g];
            const int c = 4 * g;
            atomicAdd(&ss[c + 0], c1 * b0.x); atomicAdd(&ss[c + 1], c1 * b0.y);
            atomicAdd(&ss[c + 2], c1 * b0.z); atomicAdd(&ss[c + 3], c1 * b0.w);
            atomicAdd(&ss[128 + c + 0], c1 * b1.x); atomicAdd(&ss[128 + c + 1], c1 * b1.y);
            atomicAdd(&ss[128 + c + 2], c1 * b1.z); atomicAdd(&ss[128 + c + 3], c1 * b1.w);
            atomicAdd(&ss[256 + c + 0], c1 * b0.x * b0.x); atomicAdd(&ss[256 + c + 1], c1 * b0.y * b0.y);
            atomicAdd(&ss[256 + c + 2], c1 * b0.z * b0.z); atomicAdd(&ss[256 + c + 3], c1 * b0.w * b0.w);
            atomicAdd(&ss[384 + c + 0], c1 * b1.x * b1.x); atomicAdd(&ss[384 + c + 1], c1 * b1.y * b1.y);
            atomicAdd(&ss[384 + c + 2], c1 * b1.z * b1.z); atomicAdd(&ss[384 + c + 3], c1 * b1.w * b1.w);
        }
    }
    __syncthreads();
    for (int i = tid; i < 512; i += 256)
        if (ss[i] != 0.f) atomicAdd(&g_stats1[i], ss[i]);
}

// ---------------- BN1 stats, node side: cnt0*zA(+sq) + cross via S_n -------
// one warp per node; S_n = sum of zB over the node's CSR edges.
__global__ void __launch_bounds__(256) node_side_stats(int N)
{
    __shared__ float ss[512];
    const int tid = threadIdx.x;
    for (int i = tid; i < 512; i += 256) ss[i] = 0.f;
    __syncthreads();

    const int lane = tid & 31;
    const int n = blockIdx.x * 8 + (tid >> 5);
    if (n < N) {
        const float4* zA4 = (const float4*)g_zA;
        const float4* zB4 = (const float4*)g_zB;
        float4 a0 = zA4[(size_t)n * 64 + lane];
        float4 a1 = zA4[(size_t)n * 64 + 32 + lane];
        const int base = g_base[n];
        const int cnt  = g_cnt0[n];

        float4 S0 = {0,0,0,0}, S1 = {0,0,0,0};
        int k = 0;
        for (; k + 2 <= cnt; k += 2) {
            int m0 = g_ei1[base + k];
            int m1 = g_ei1[base + k + 1];
            float4 p0 = zB4[(size_t)m0 * 64 + lane];
            float4 p1 = zB4[(size_t)m0 * 64 + 32 + lane];
            float4 q0 = zB4[(size_t)m1 * 64 + lane];
            float4 q1 = zB4[(size_t)m1 * 64 + 32 + lane];
            S0 = f4add(S0, f4add(p0, q0));
            S1 = f4add(S1, f4add(p1, q1));
        }
        if (k < cnt) {
            int m0 = g_ei1[base + k];
            S0 = f4add(S0, zB4[(size_t)m0 * 64 + lane]);
            S1 = f4add(S1, zB4[(size_t)m0 * 64 + 32 + lane]);
        }

        const float cf = (float)cnt;
        const int c = 4 * lane;
        // sum  += cnt*zA + S ; sumsq += cnt*zA^2 + 2*zA*S
        atomicAdd(&ss[c + 0], cf * a0.x + S0.x);
        atomicAdd(&ss[c + 1], cf * a0.y + S0.y);
        atomicAdd(&ss[c + 2], cf * a0.z + S0.z);
        atomicAdd(&ss[c + 3], cf * a0.w + S0.w);
        atomicAdd(&ss[128 + c + 0], cf * a1.x + S1.x);
        atomicAdd(&ss[128 + c + 1], cf * a1.y + S1.y);
        atomicAdd(&ss[128 + c + 2], cf * a1.z + S1.z);
        atomicAdd(&ss[128 + c + 3], cf * a1.w + S1.w);
        atomicAdd(&ss[256 + c + 0], cf * a0.x * a0.x + 2.f * a0.x * S0.x);
        atomicAdd(&ss[256 + c + 1], cf * a0.y * a0.y + 2.f * a0.y * S0.y);
        atomicAdd(&ss[256 + c + 2], cf * a0.z * a0.z + 2.f * a0.z * S0.z);
        atomicAdd(&ss[256 + c + 3], cf * a0.w * a0.w + 2.f * a0.w * S0.w);
        atomicAdd(&ss[384 + c + 0], cf * a1.x * a1.x + 2.f * a1.x * S1.x);
        atomicAdd(&ss[384 + c + 1], cf * a1.y * a1.y + 2.f * a1.y * S1.y);
        atomicAdd(&ss[384 + c + 2], cf * a1.z * a1.z + 2.f * a1.z * S1.z);
        atomicAdd(&ss[384 + c + 3], cf * a1.w * a1.w + 2.f * a1.w * S1.w);
    }
    __syncthreads();
    for (int i = tid; i < 512; i += 256)
        if (ss[i] != 0.f) atomicAdd(&g_stats1[i], ss[i]);
}

// ---------------- BN finalize ----------------------------------------------
__global__ void bn_finalize(const float* __restrict__ stats,
                            const float* __restrict__ gma,
                            const float* __restrict__ bta,
                            float inv, int C,
                            float* __restrict__ scale, float* __restrict__ shift)
{
    const int c = blockIdx.x * blockDim.x + threadIdx.x;
    if (c < C) {
        float mean = stats[c] * inv;
        float var  = stats[C + c] * inv - mean * mean;
        float s    = gma[c] * rsqrtf(var + 1e-5f);
        scale[c] = s;
        shift[c] = bta[c] - mean * s;
    }
}

// ---------------- message + softmax aggregation (warp per node, CSR) -------
// also accumulates BN2 statistics of out = num/den.
__global__ void __launch_bounds__(256) node_aggregate(
    const float* __restrict__ aggr_t, int N)
{
    __shared__ float ss[256];
    const int tid = threadIdx.x;
    for (int i = tid; i < 256; i += 256) ss[i] = 0.f;
    __syncthreads();

    const int lane = tid & 31;
    const int n = blockIdx.x * 8 + (tid >> 5);
    if (n < N) {
        const float4* zA4 = (const float4*)g_zA;
        const float4* zB4 = (const float4*)g_zB;
        const float4 sf = *(const float4*)&g_scale1[4 * lane];
        const float4 tf = *(const float4*)&g_shift1[4 * lane];
        const float4 sc = *(const float4*)&g_scale1[128 + 4 * lane];
        const float4 tc = *(const float4*)&g_shift1[128 + 4 * lane];
        const float  T  = *aggr_t;

        float4 a0 = zA4[(size_t)n * 64 + lane];
        float4 a1 = zA4[(size_t)n * 64 + 32 + lane];
        // fold zA into the affine: z*s+t = (zA+zB)*s+t = (zA*s+t) + zB*s
        float4 af = {a0.x * sf.x + tf.x, a0.y * sf.y + tf.y,
                     a0.z * sf.z + tf.z, a0.w * sf.w + tf.w};
        float4 ac = {a1.x * sc.x + tc.x, a1.y * sc.y + tc.y,
                     a1.z * sc.z + tc.z, a1.w * sc.w + tc.w};

        const int base = g_base[n];
        const int cnt  = g_cnt0[n];

        float nx = 0, ny = 0, nz = 0, nw = 0;
        float dx = 0, dy = 0, dz = 0, dw = 0;
        for (int k = 0; k < cnt; k++) {
            int m = g_ei1[base + k];
            float4 b0 = zB4[(size_t)m * 64 + lane];
            float4 b1 = zB4[(size_t)m * 64 + 32 + lane];
            float zfx = af.x + b0.x * sf.x;
            float zfy = af.y + b0.y * sf.y;
            float zfz = af.z + b0.z * sf.z;
            float zfw = af.w + b0.w * sf.w;
            float zcx = ac.x + b1.x * sc.x;
            float zcy = ac.y + b1.y * sc.y;
            float zcz = ac.z + b1.z * sc.z;
            float zcw = ac.w + b1.w * sc.w;
            float mx = sigmoidf(zfx) * softplusf(zcx);
            float my = sigmoidf(zfy) * softplusf(zcy);
            float mz = sigmoidf(zfz) * softplusf(zcz);
            float mw = sigmoidf(zfw) * softplusf(zcw);
            float ex = __expf(T * mx);
            float ey = __expf(T * my);
            float ez = __expf(T * mz);
            float ew = __expf(T * mw);
            dx += ex; dy += ey; dz += ez; dw += ew;
            nx += mx * ex; ny += my * ey; nz += mz * ez; nw += mw * ew;
        }

        float ox = nx / (dx + 1e-16f);
        float oy = ny / (dy + 1e-16f);
        float oz = nz / (dz + 1e-16f);
        float ow = nw / (dw + 1e-16f);

        float4 o = {ox, oy, oz, ow};
        ((float4*)g_out)[(size_t)n * 32 + lane] = o;

        const int c = 4 * lane;
        atomicAdd(&ss[c + 0], ox); atomicAdd(&ss[c + 1], oy);
        atomicAdd(&ss[c + 2], oz); atomicAdd(&ss[c + 3], ow);
        atomicAdd(&ss[128 + c + 0], ox * ox); atomicAdd(&ss[128 + c + 1], oy * oy);
        atomicAdd(&ss[128 + c + 2], oz * oz); atomicAdd(&ss[128 + c + 3], ow * ow);
    }
    __syncthreads();
    for (int i = tid; i < 256; i += 256)
        if (ss[i] != 0.f) atomicAdd(&g_stats2[i], ss[i]);
}

// ---------------- node final: h' = softplus(BN2(out)+h); pool + counts -----
__global__ void __launch_bounds__(256) node_final(
    const int* __restrict__ batch, int N)
{
    const int gid = blockIdx.x * 256 + threadIdx.x;
    const int n = gid >> 5;
    const int g = gid & 31;
    if (n >= N) return;

    float4 o  = ((const float4*)g_out)[(size_t)n * 32 + g];
    float4 s2 = *(const float4*)&g_scale2[4 * g];
    float4 t2 = *(const float4*)&g_shift2[4 * g];
    float4 hv = ((const float4*)g_h)[(size_t)n * 32 + g];

    float vx = softplusf(o.x * s2.x + t2.x + hv.x);
    float vy = softplusf(o.y * s2.y + t2.y + hv.y);
    float vz = softplusf(o.z * s2.z + t2.z + hv.z);
    float vw = softplusf(o.w * s2.w + t2.w + hv.w);

    const int b = batch[n];
    if (g == 0) atomicAdd(&g_counts[b], 1.f);
    red_add_v4(&g_pooled[(size_t)b * 128 + 4 * g], vx, vy, vz, vw);
}

// ---------------- head: mean pool -> softplus(MLP) -> linear ---------------
__global__ void __launch_bounds__(256) head(
    const float* __restrict__ l1_w, const float* __restrict__ l1_b,
    const float* __restrict__ out_w, const float* __restrict__ out_b,
    float* __restrict__ out)
{
    __shared__ float p[128];
    __shared__ float red[256];
    const int g = blockIdx.x;
    const int tid = threadIdx.x;
    if (tid < 128)
        p[tid] = g_pooled[g * 128 + tid] / fmaxf(g_counts[g], 1.f);
    __syncthreads();

    float acc = l1_b[tid];
    #pragma unroll 8
    for (int k = 0; k < 128; k++)
        acc += p[k] * l1_w[k * 256 + tid];
    red[tid] = softplusf(acc) * out_w[tid];
    __syncthreads();
    for (int s = 128; s > 0; s >>= 1) {
        if (tid < s) red[tid] += red[tid + s];
        __syncthreads();
    }
    if (tid == 0) out[g] = red[0] + out_b[0];
}

// ---------------- launch ---------------------------------------------------
extern "C" void kernel_launch(void* const* d_in, const int* in_sizes, int n_in,
                              void* d_out, int out_size)
{
    const float* x        = (const float*)d_in[0];
    const float* hedge    = (const float*)d_in[1];
    const int*   rel      = (const int*)d_in[2];      // int32 (JAX x64 disabled)
    const int*   batch    = (const int*)d_in[3];      // int32
    const float* embed_w  = (const float*)d_in[5];
    const float* embed_b  = (const float*)d_in[6];
    const float* bembed_w = (const float*)d_in[7];
    const float* bembed_b = (const float*)d_in[8];
    const float* lin_w    = (const float*)d_in[9];
    const float* lin_b    = (const float*)d_in[10];
    const float* bn1_g    = (const float*)d_in[11];
    const float* bn1_b    = (const float*)d_in[12];
    const float* bn2_g    = (const float*)d_in[13];
    const float* bn2_b    = (const float*)d_in[14];
    const float* aggr_t   = (const float*)d_in[15];
    const float* l1_w     = (const float*)d_in[16];
    const float* l1_b     = (const float*)d_in[17];
    const float* out_w    = (const float*)d_in[18];
    const float* out_b    = (const float*)d_in[19];

    const int N   = in_sizes[0] / 92;
    const int NHE = in_sizes[1] / 40;
    const int E   = in_sizes[2] / 3;
    const int* idx0 = rel;
    const int* idx1 = rel + E;

    void *p_h, *p_cf, *p_zA, *p_zB;
    void *p_st1, *p_sc1, *p_sh1, *p_st2, *p_sc2, *p_sh2, *p_pool, *p_cnt;
    void *p_c0, *p_c1;
    cudaGetSymbolAddress(&p_h,   g_h);
    cudaGetSymbolAddress(&p_cf,  g_cf);
    cudaGetSymbolAddress(&p_zA,  g_zA);
    cudaGetSymbolAddress(&p_zB,  g_zB);
    cudaGetSymbolAddress(&p_st1, g_stats1);
    cudaGetSymbolAddress(&p_sc1, g_scale1);
    cudaGetSymbolAddress(&p_sh1, g_shift1);
    cudaGetSymbolAddress(&p_st2, g_stats2);
    cudaGetSymbolAddress(&p_sc2, g_scale2);
    cudaGetSymbolAddress(&p_sh2, g_shift2);
    cudaGetSymbolAddress(&p_pool, g_pooled);
    cudaGetSymbolAddress(&p_cnt,  g_counts);
    cudaGetSymbolAddress(&p_c0,   g_cnt0);
    cudaGetSymbolAddress(&p_c1,   g_cnt1);

    cudaMemsetAsync(p_c0,  0, N * sizeof(int));
    cudaMemsetAsync(p_c1,  0, NHE * sizeof(int));
    cudaMemsetAsync(p_st1, 0, 2 * CDIM * sizeof(float));
    cudaMemsetAsync(p_st2, 0, 2 * HDIM * sizeof(float));
    cudaMemsetAsync(p_pool, 0, GNUM * HDIM * sizeof(float));
    cudaMemsetAsync(p_cnt,  0, GNUM * sizeof(float));

    const dim3 t256(256);
    const int mbN   = (N   + 127) / 128;
    const int mbNHE = (NHE + 127) / 128;

    // embeddings + factored edge-linear
    sgemm<<<dim3(mbN, 1),   t256>>>(x,     embed_w,  nullptr, embed_b,  (float*)p_h,  N,   128, 92);
    sgemm<<<dim3(mbNHE, 1), t256>>>(hedge, bembed_w, nullptr, bembed_b, (float*)p_cf, NHE, 128, 40);
    sgemm<<<dim3(mbN, 2),   t256>>>((float*)p_h,  lin_w,             lin_w + 256 * 256, nullptr, (float*)p_zA, N,   256, 128);
    sgemm<<<dim3(mbNHE, 2), t256>>>((float*)p_cf, lin_w + 128 * 256, nullptr,           lin_b,   (float*)p_zB, NHE, 256, 128);

    // CSR build (independent of GEMMs; runs on same stream)
    count_edges<<<1184, t256>>>(idx0, idx1, E);
    scan_counts<<<1, 1024>>>(N);
    scatter_edges<<<1184, t256>>>(idx0, idx1, E);

    // BN1 stats (factored: hyperedge-side degree-weighted + node-side w/ cross term)
    hedge_stats<<<(NHE * 32 + 255) / 256, t256>>>(NHE);
    node_side_stats<<<(N + 7) / 8, t256>>>(N);
    bn_finalize<<<1, 256>>>((float*)p_st1, bn1_g, bn1_b, 1.0f / (float)E, 256,
                            (float*)p_sc1, (float*)p_sh1);

    // message + softmax aggregation + BN2 stats
    node_aggregate<<<(N + 7) / 8, t256>>>(aggr_t, N);
    bn_finalize<<<1, 128>>>((float*)p_st2, bn2_g, bn2_b, 1.0f / (float)N, 128,
                            (float*)p_sc2, (float*)p_sh2);

    node_final<<<(N * 32 + 255) / 256, t256>>>(batch, N);
    head<<<GNUM, t256>>>(l1_w, l1_b, out_w, out_b, (float*)d_out);
}

// round 14
// speedup vs baseline: 1.2291x; 1.1976x over previous
#include <cuda_runtime.h>

// ---------------- problem constants (shapes fixed by the dataset) ----------
#define NMAX   50000
#define EMAX   800000
#define HDIM   128
#define CDIM   256      // 2*H
#define GNUM   128

// ---------------- scratch (static device globals; no runtime allocation) --
__device__ __align__(16) float g_h     [NMAX * HDIM];     // node embeddings      [N,128]
__device__ __align__(16) float g_zA    [NMAX * CDIM];     // x @ W1 + b1          [N,256]
__device__ __align__(16) float g_zB    [NMAX * CDIM];     // hedge @ W2 + b2      [NHE,256]
__device__ __align__(16) float g_out   [NMAX * HDIM];     // aggregated msgs      [N,128]
__device__ __align__(16) float g_W1    [92 * CDIM];       // embed_w @ (Wa+Wc)
__device__ __align__(16) float g_b1    [CDIM];
__device__ __align__(16) float g_W2    [40 * CDIM];       // bembed_w @ Wb
__device__ __align__(16) float g_b2    [CDIM];
__device__ __align__(16) float g_S     [NMAX * 48];       // per-node seg-sum of hedge rows [N,48]
__device__ __align__(16) float g_K     [93 * 48];         // x^e^T @ S  [93,41] padded
__device__ __align__(16) float g_stats1[2 * CDIM];        // BN1 sum / sumsq
__device__ __align__(16) float g_scale1[CDIM];
__device__ __align__(16) float g_shift1[CDIM];
__device__ __align__(16) float g_stats2[2 * HDIM];        // BN2 sum / sumsq
__device__ __align__(16) float g_scale2[HDIM];
__device__ __align__(16) float g_shift2[HDIM];
__device__ __align__(16) float g_pooled[GNUM * HDIM];
__device__ __align__(16) float g_counts[GNUM];
// CSR scratch
__device__ int g_cnt0  [NMAX];      // node in-degree (i0)
__device__ int g_cnt1  [NMAX];      // hyperedge degree (i1)
__device__ int g_base  [NMAX];      // exclusive prefix of cnt0
__device__ int g_cursor[NMAX];      // scatter cursors
__device__ int g_ei1   [EMAX];      // i1 of edges, grouped by i0

// ---------------- helpers --------------------------------------------------
static __device__ __forceinline__ float softplusf_fast(float x) {
    // stable: max(x,0) + log(1 + exp(-|x|)); arg of log in [1,2]
    return fmaxf(x, 0.f) + __logf(1.f + __expf(-fabsf(x)));
}
static __device__ __forceinline__ float sigmoidf_fast(float x) {
    return __fdividef(1.f, 1.f + __expf(-x));
}
static __device__ __forceinline__ void red_add_v4(float* p, float a, float b, float c, float d) {
    asm volatile("red.global.add.v4.f32 [%0], {%1, %2, %3, %4};"
                 :: "l"(p), "f"(a), "f"(b), "f"(c), "f"(d) : "memory");
}

// ---------------- generic fp32 GEMM: C[M,N] = A[M,K] @ B[K,N] + bias -------
__global__ void __launch_bounds__(256) sgemm(
    const float* __restrict__ A, const float* __restrict__ B1,
    const float* __restrict__ bias,
    float* __restrict__ C, int M, int N, int K)
{
    __shared__ float As[16][128];
    __shared__ float Bs[16][128];

    const int tid = threadIdx.x;
    const int m0  = blockIdx.x * 128;
    const int n0  = blockIdx.y * 128;
    const int tm  = tid >> 4;
    const int tn  = tid & 15;

    const int lm  = tid >> 1;
    const int lk  = (tid & 1) * 8;
    const int lkB = tid >> 4;
    const int lnB = (tid & 15) * 8;

    float acc[8][8];
    #pragma unroll
    for (int i = 0; i < 8; i++)
        #pragma unroll
        for (int j = 0; j < 8; j++) acc[i][j] = 0.f;

    for (int k0 = 0; k0 < K; k0 += 16) {
        {
            const int row = m0 + lm;
            if (row < M && (k0 + 16 <= K)) {
                const float* ap = A + (long long)row * K + k0 + lk;
                float4 v0 = *(const float4*)(ap);
                float4 v1 = *(const float4*)(ap + 4);
                As[lk + 0][lm] = v0.x; As[lk + 1][lm] = v0.y;
                As[lk + 2][lm] = v0.z; As[lk + 3][lm] = v0.w;
                As[lk + 4][lm] = v1.x; As[lk + 5][lm] = v1.y;
                As[lk + 6][lm] = v1.z; As[lk + 7][lm] = v1.w;
            } else {
                #pragma unroll
                for (int i = 0; i < 8; i++) {
                    int kk = k0 + lk + i;
                    As[lk + i][lm] = (row < M && kk < K)
                                   ? A[(long long)row * K + kk] : 0.f;
                }
            }
        }
        {
            const int kk = k0 + lkB;
            float4 v0 = {0,0,0,0}, v1 = {0,0,0,0};
            if (kk < K) {
                const float* bp = B1 + (long long)kk * N + n0 + lnB;
                v0 = *(const float4*)bp;
                v1 = *(const float4*)(bp + 4);
            }
            *(float4*)&Bs[lkB][lnB]     = v0;
            *(float4*)&Bs[lkB][lnB + 4] = v1;
        }
        __syncthreads();

        #pragma unroll
        for (int kk = 0; kk < 16; kk++) {
            float a[8], b[8];
            *(float4*)(a)     = *(const float4*)&As[kk][tm * 8];
            *(float4*)(a + 4) = *(const float4*)&As[kk][tm * 8 + 4];
            *(float4*)(b)     = *(const float4*)&Bs[kk][tn * 8];
            *(float4*)(b + 4) = *(const float4*)&Bs[kk][tn * 8 + 4];
            #pragma unroll
            for (int i = 0; i < 8; i++)
                #pragma unroll
                for (int j = 0; j < 8; j++)
                    acc[i][j] += a[i] * b[j];
        }
        __syncthreads();
    }

    float bs[8];
    #pragma unroll
    for (int j = 0; j < 8; j++)
        bs[j] = bias ? bias[n0 + tn * 8 + j] : 0.f;

    #pragma unroll
    for (int i = 0; i < 8; i++) {
        const int row = m0 + tm * 8 + i;
        if (row < M) {
            float* cp = C + (long long)row * N + n0 + tn * 8;
            float4 o0 = {acc[i][0] + bs[0], acc[i][1] + bs[1],
                         acc[i][2] + bs[2], acc[i][3] + bs[3]};
            float4 o1 = {acc[i][4] + bs[4], acc[i][5] + bs[5],
                         acc[i][6] + bs[6], acc[i][7] + bs[7]};
            *(float4*)(cp)     = o0;
            *(float4*)(cp + 4) = o1;
        }
    }
}

// ---------------- weight prep: fold embed into conv linear -----------------
// W1[i][c] = sum_j embed_w[i][j] * (lin_w[j][c] + lin_w[256+j][c]); row 92 = bias
__global__ void __launch_bounds__(256) w1prep(
    const float* __restrict__ embed_w, const float* __restrict__ embed_b,
    const float* __restrict__ lin_w)
{
    const int i = blockIdx.x;       // 0..92
    const int c = threadIdx.x;      // 0..255
    float acc = 0.f;
    #pragma unroll 4
    for (int j = 0; j < 128; j++) {
        float we = (i < 92) ? embed_w[i * 128 + j] : embed_b[j];
        acc += we * (lin_w[j * 256 + c] + lin_w[(256 + j) * 256 + c]);
    }
    if (i < 92) g_W1[i * 256 + c] = acc; else g_b1[c] = acc;
}

// W2[i][c] = sum_j bembed_w[i][j] * lin_w[128+j][c]; row 40 = bias (+lin_b)
__global__ void __launch_bounds__(256) w2prep(
    const float* __restrict__ bembed_w, const float* __restrict__ bembed_b,
    const float* __restrict__ lin_w, const float* __restrict__ lin_b)
{
    const int i = blockIdx.x;       // 0..40
    const int c = threadIdx.x;
    float acc = (i == 40) ? lin_b[c] : 0.f;
    #pragma unroll 4
    for (int j = 0; j < 128; j++) {
        float bw = (i < 40) ? bembed_w[i * 128 + j] : bembed_b[j];
        acc += bw * lin_w[(128 + j) * 256 + c];
    }
    if (i < 40) g_W2[i * 256 + c] = acc; else g_b2[c] = acc;
}

// ---------------- CSR build ------------------------------------------------
__global__ void __launch_bounds__(256) count_edges(
    const int* __restrict__ idx0, const int* __restrict__ idx1, int E)
{
    for (int e = blockIdx.x * 256 + threadIdx.x; e < E; e += gridDim.x * 256) {
        atomicAdd(&g_cnt0[idx0[e]], 1);
        atomicAdd(&g_cnt1[idx1[e]], 1);
    }
}

__global__ void __launch_bounds__(1024) scan_counts(int N)
{
    __shared__ int sh[1024];
    const int tid   = threadIdx.x;
    const int chunk = (N + 1023) / 1024;
    const int start = tid * chunk;
    const int end   = min(start + chunk, N);

    int s = 0;
    for (int i = start; i < end; i++) s += g_cnt0[i];
    sh[tid] = s;
    __syncthreads();
    for (int off = 1; off < 1024; off <<= 1) {
        int v = (tid >= off) ? sh[tid - off] : 0;
        __syncthreads();
        sh[tid] += v;
        __syncthreads();
    }
    int run = sh[tid] - s;
    for (int i = start; i < end; i++) {
        int c = g_cnt0[i];
        g_base[i]   = run;
        g_cursor[i] = run;
        run += c;
    }
}

__global__ void __launch_bounds__(256) scatter_edges(
    const int* __restrict__ idx0, const int* __restrict__ idx1, int E)
{
    for (int e = blockIdx.x * 256 + threadIdx.x; e < E; e += gridDim.x * 256) {
        int p = atomicAdd(&g_cursor[idx0[e]], 1);
        g_ei1[p] = idx1[e];
    }
}

// ---------------- S[n] = seg-sum of hedge rows over node n's edges ---------
// warp per node; cols 0..39 = raw hedge attrs, col 40 = cnt0[n] (bias column)
__global__ void __launch_bounds__(256) shedge_gather(
    const float* __restrict__ hedge, int N)
{
    const int tid  = threadIdx.x;
    const int lane = tid & 31;
    const int n    = blockIdx.x * 8 + (tid >> 5);
    if (n >= N) return;

    const int base = g_base[n];
    const int cnt  = g_cnt0[n];
    float lo = 0.f, hi = 0.f;
    int k = 0;
    for (; k + 2 <= cnt; k += 2) {
        int m0 = g_ei1[base + k];
        int m1 = g_ei1[base + k + 1];
        const float* h0 = hedge + (size_t)m0 * 40;
        const float* h1 = hedge + (size_t)m1 * 40;
        lo += h0[lane] + h1[lane];
        if (lane < 8) hi += h0[32 + lane] + h1[32 + lane];
    }
    if (k < cnt) {
        const float* h0 = hedge + (size_t)g_ei1[base + k] * 40;
        lo += h0[lane];
        if (lane < 8) hi += h0[32 + lane];
    }
    g_S[(size_t)n * 48 + lane] = lo;
    if (lane < 8)  g_S[(size_t)n * 48 + 32 + lane] = hi;
    if (lane == 0) g_S[(size_t)n * 48 + 40] = (float)cnt;
}

// ---------------- K[93,41] = x^e^T @ S (tall-K small-output GEMM) ----------
__global__ void __launch_bounds__(256) kgemm(const float* __restrict__ x, int N)
{
    __shared__ __align__(16) float sx[64][96];   // x^e rows (col 92 = 1)
    __shared__ __align__(16) float sS[64][48];
    const int tid = threadIdx.x;

    // task = i*11 + jq ; i in [0,93), jq in [0,11), j0 = 4*jq
    int task[4], ti[4], tj[4];
    float4 acc[4];
    #pragma unroll
    for (int t = 0; t < 4; t++) {
        task[t] = tid + t * 256;
        ti[t] = task[t] / 11;
        tj[t] = (task[t] % 11) * 4;
        acc[t] = make_float4(0.f, 0.f, 0.f, 0.f);
    }

    for (int n0 = blockIdx.x * 64; n0 < N; n0 += gridDim.x * 64) {
        // load x tile
        for (int idx = tid; idx < 64 * 92; idx += 256) {
            int r = idx / 92, c = idx % 92;
            int n = n0 + r;
            sx[r][c] = (n < N) ? x[(size_t)n * 92 + c] : 0.f;
        }
        if (tid < 64) sx[tid][92] = (n0 + tid < N) ? 1.f : 0.f;
        // load S tile
        for (int idx = tid; idx < 64 * 48; idx += 256) {
            int r = idx / 48, c = idx % 48;
            int n = n0 + r;
            sS[r][c] = (n < N) ? g_S[(size_t)n * 48 + c] : 0.f;
        }
        __syncthreads();

        for (int r = 0; r < 64; r++) {
            #pragma unroll
            for (int t = 0; t < 4; t++) {
                if (task[t] < 1023) {
                    float a = sx[r][ti[t]];
                    float4 v = *(const float4*)&sS[r][tj[t]];
                    acc[t].x += a * v.x; acc[t].y += a * v.y;
                    acc[t].z += a * v.z; acc[t].w += a * v.w;
                }
            }
        }
        __syncthreads();
    }

    #pragma unroll
    for (int t = 0; t < 4; t++) {
        if (task[t] < 1023) {
            float* kp = &g_K[ti[t] * 48 + tj[t]];
            atomicAdd(kp + 0, acc[t].x);
            atomicAdd(kp + 1, acc[t].y);
            atomicAdd(kp + 2, acc[t].z);
            atomicAdd(kp + 3, acc[t].w);
        }
    }
}

// ---------------- cross term: stats1[256+c] += 2 * W1e[:,c]^T K W2e[:,c] ---
__global__ void __launch_bounds__(256) cross_add()
{
    __shared__ float kr[48];
    const int i = blockIdx.x;      // 0..92
    const int c = threadIdx.x;
    if (c < 48) kr[c] = g_K[i * 48 + c];
    __syncthreads();

    float inner = g_b2[c] * kr[40];
    #pragma unroll 4
    for (int j = 0; j < 40; j++)
        inner += kr[j] * g_W2[j * 256 + c];
    float w1 = (i < 92) ? g_W1[i * 256 + c] : g_b1[c];
    atomicAdd(&g_stats1[256 + c], 2.f * w1 * inner);
}

// ---------------- degree-weighted self sums into BN1 stats -----------------
__global__ void __launch_bounds__(256) weighted_stats(
    const float* __restrict__ Z, const int* __restrict__ cnt, int R)
{
    __shared__ float ss[512];
    const int tid = threadIdx.x;
    for (int i = tid; i < 512; i += 256) ss[i] = 0.f;
    __syncthreads();

    const int gid = blockIdx.x * 256 + tid;
    const int r = gid >> 5;
    const int g = gid & 31;
    if (r < R) {
        const float w = (float)cnt[r];
        if (w > 0.f) {
            const float4* Z4 = (const float4*)Z;
            float4 z0 = Z4[(size_t)r * 64 + g];
            float4 z1 = Z4[(size_t)r * 64 + 32 + g];
            const int c = 4 * g;
            atomicAdd(&ss[c + 0], w * z0.x); atomicAdd(&ss[c + 1], w * z0.y);
            atomicAdd(&ss[c + 2], w * z0.z); atomicAdd(&ss[c + 3], w * z0.w);
            atomicAdd(&ss[128 + c + 0], w * z1.x); atomicAdd(&ss[128 + c + 1], w * z1.y);
            atomicAdd(&ss[128 + c + 2], w * z1.z); atomicAdd(&ss[128 + c + 3], w * z1.w);
            atomicAdd(&ss[256 + c + 0], w * z0.x * z0.x); atomicAdd(&ss[256 + c + 1], w * z0.y * z0.y);
            atomicAdd(&ss[256 + c + 2], w * z0.z * z0.z); atomicAdd(&ss[256 + c + 3], w * z0.w * z0.w);
            atomicAdd(&ss[384 + c + 0], w * z1.x * z1.x); atomicAdd(&ss[384 + c + 1], w * z1.y * z1.y);
            atomicAdd(&ss[384 + c + 2], w * z1.z * z1.z); atomicAdd(&ss[384 + c + 3], w * z1.w * z1.w);
        }
    }
    __syncthreads();
    for (int i = tid; i < 512; i += 256)
        if (ss[i] != 0.f) atomicAdd(&g_stats1[i], ss[i]);
}

// ---------------- BN finalize ----------------------------------------------
__global__ void bn_finalize(const float* __restrict__ stats,
                            const float* __restrict__ gma,
                            const float* __restrict__ bta,
                            float inv, int C,
                            float* __restrict__ scale, float* __restrict__ shift)
{
    const int c = blockIdx.x * blockDim.x + threadIdx.x;
    if (c < C) {
        float mean = stats[c] * inv;
        float var  = fmaxf(stats[C + c] * inv - mean * mean, 0.f);
        float s    = gma[c] * rsqrtf(var + 1e-5f);
        scale[c] = s;
        shift[c] = bta[c] - mean * s;
    }
}

// ---------------- message + softmax aggregation (warp per node, CSR) -------
__global__ void __launch_bounds__(256) node_aggregate(
    const float* __restrict__ aggr_t, int N)
{
    __shared__ float ss[256];
    const int tid = threadIdx.x;
    ss[tid] = 0.f;
    __syncthreads();

    const int lane = tid & 31;
    const int n = blockIdx.x * 8 + (tid >> 5);
    if (n < N) {
        const float4* zA4 = (const float4*)g_zA;
        const float4* zB4 = (const float4*)g_zB;
        const float4 sf = *(const float4*)&g_scale1[4 * lane];
        const float4 tf = *(const float4*)&g_shift1[4 * lane];
        const float4 sc = *(const float4*)&g_scale1[128 + 4 * lane];
        const float4 tc = *(const float4*)&g_shift1[128 + 4 * lane];
        const float  T  = *aggr_t;

        float4 a0 = zA4[(size_t)n * 64 + lane];
        float4 a1 = zA4[(size_t)n * 64 + 32 + lane];
        const float4 af = {a0.x * sf.x + tf.x, a0.y * sf.y + tf.y,
                           a0.z * sf.z + tf.z, a0.w * sf.w + tf.w};
        const float4 ac = {a1.x * sc.x + tc.x, a1.y * sc.y + tc.y,
                           a1.z * sc.z + tc.z, a1.w * sc.w + tc.w};

        const int base = g_base[n];
        const int cnt  = g_cnt0[n];

        float nx = 0, ny = 0, nz = 0, nw = 0;
        float dx = 0, dy = 0, dz = 0, dw = 0;

        #define PROC(mIdx)                                                    \
        {                                                                     \
            float4 b0 = zB4[(size_t)(mIdx) * 64 + lane];                      \
            float4 b1 = zB4[(size_t)(mIdx) * 64 + 32 + lane];                 \
            float mx = sigmoidf_fast(af.x + b0.x * sf.x) *                    \
                       softplusf_fast(ac.x + b1.x * sc.x);                    \
            float my = sigmoidf_fast(af.y + b0.y * sf.y) *                    \
                       softplusf_fast(ac.y + b1.y * sc.y);                    \
            float mz = sigmoidf_fast(af.z + b0.z * sf.z) *                    \
                       softplusf_fast(ac.z + b1.z * sc.z);                    \
            float mw = sigmoidf_fast(af.w + b0.w * sf.w) *                    \
                       softplusf_fast(ac.w + b1.w * sc.w);                    \
            float ex = __expf(T * mx); float ey = __expf(T * my);             \
            float ez = __expf(T * mz); float ew = __expf(T * mw);             \
            dx += ex; dy += ey; dz += ez; dw += ew;                           \
            nx += mx * ex; ny += my * ey; nz += mz * ez; nw += mw * ew;       \
        }

        int k = 0;
        for (; k + 2 <= cnt; k += 2) {
            int m0 = g_ei1[base + k];
            int m1 = g_ei1[base + k + 1];
            PROC(m0);
            PROC(m1);
        }
        if (k < cnt) {
            int m0 = g_ei1[base + k];
            PROC(m0);
        }
        #undef PROC

        float ox = nx / (dx + 1e-16f);
        float oy = ny / (dy + 1e-16f);
        float oz = nz / (dz + 1e-16f);
        float ow = nw / (dw + 1e-16f);

        ((float4*)g_out)[(size_t)n * 32 + lane] = make_float4(ox, oy, oz, ow);

        const int c = 4 * lane;
        atomicAdd(&ss[c + 0], ox); atomicAdd(&ss[c + 1], oy);
        atomicAdd(&ss[c + 2], oz); atomicAdd(&ss[c + 3], ow);
        atomicAdd(&ss[128 + c + 0], ox * ox); atomicAdd(&ss[128 + c + 1], oy * oy);
        atomicAdd(&ss[128 + c + 2], oz * oz); atomicAdd(&ss[128 + c + 3], ow * ow);
    }
    __syncthreads();
    if (ss[tid] != 0.f) atomicAdd(&g_stats2[tid], ss[tid]);
}

// ---------------- node final: h' = softplus(BN2(out)+h); pool + counts -----
__global__ void __launch_bounds__(256) node_final(
    const int* __restrict__ batch, int N)
{
    const int gid = blockIdx.x * 256 + threadIdx.x;
    const int n = gid >> 5;
    const int g = gid & 31;
    if (n >= N) return;

    float4 o  = ((const float4*)g_out)[(size_t)n * 32 + g];
    float4 s2 = *(const float4*)&g_scale2[4 * g];
    float4 t2 = *(const float4*)&g_shift2[4 * g];
    float4 hv = ((const float4*)g_h)[(size_t)n * 32 + g];

    float vx = softplusf_fast(o.x * s2.x + t2.x + hv.x);
    float vy = softplusf_fast(o.y * s2.y + t2.y + hv.y);
    float vz = softplusf_fast(o.z * s2.z + t2.z + hv.z);
    float vw = softplusf_fast(o.w * s2.w + t2.w + hv.w);

    const int b = batch[n];
    if (g == 0) atomicAdd(&g_counts[b], 1.f);
    red_add_v4(&g_pooled[(size_t)b * 128 + 4 * g], vx, vy, vz, vw);
}

// ---------------- head: mean pool -> softplus(MLP) -> linear ---------------
__global__ void __launch_bounds__(256) head(
    const float* __restrict__ l1_w, const float* __restrict__ l1_b,
    const float* __restrict__ out_w, const float* __restrict__ out_b,
    float* __restrict__ out)
{
    __shared__ float p[128];
    __shared__ float red[256];
    const int g = blockIdx.x;
    const int tid = threadIdx.x;
    if (tid < 128)
        p[tid] = g_pooled[g * 128 + tid] / fmaxf(g_counts[g], 1.f);
    __syncthreads();

    float acc = l1_b[tid];
    #pragma unroll 8
    for (int k = 0; k < 128; k++)
        acc += p[k] * l1_w[k * 256 + tid];
    red[tid] = softplusf_fast(acc) * out_w[tid];
    __syncthreads();
    for (int s = 128; s > 0; s >>= 1) {
        if (tid < s) red[tid] += red[tid + s];
        __syncthreads();
    }
    if (tid == 0) out[g] = red[0] + out_b[0];
}

// ---------------- launch ---------------------------------------------------
extern "C" void kernel_launch(void* const* d_in, const int* in_sizes, int n_in,
                              void* d_out, int out_size)
{
    const float* x        = (const float*)d_in[0];
    const float* hedge    = (const float*)d_in[1];
    const int*   rel      = (const int*)d_in[2];      // int32 (JAX x64 disabled)
    const int*   batch    = (const int*)d_in[3];      // int32
    const float* embed_w  = (const float*)d_in[5];
    const float* embed_b  = (const float*)d_in[6];
    const float* bembed_w = (const float*)d_in[7];
    const float* bembed_b = (const float*)d_in[8];
    const float* lin_w    = (const float*)d_in[9];
    const float* lin_b    = (const float*)d_in[10];
    const float* bn1_g    = (const float*)d_in[11];
    const float* bn1_b    = (const float*)d_in[12];
    const float* bn2_g    = (const float*)d_in[13];
    const float* bn2_b    = (const float*)d_in[14];
    const float* aggr_t   = (const float*)d_in[15];
    const float* l1_w     = (const float*)d_in[16];
    const float* l1_b     = (const float*)d_in[17];
    const float* out_w    = (const float*)d_in[18];
    const float* out_b    = (const float*)d_in[19];

    const int N   = in_sizes[0] / 92;
    const int NHE = in_sizes[1] / 40;
    const int E   = in_sizes[2] / 3;
    const int* idx0 = rel;
    const int* idx1 = rel + E;

    // side stream + events for fork-join (created once, reused; capture-legal)
    static cudaStream_t s2 = nullptr;
    static cudaEvent_t evFork = nullptr, evJoin = nullptr;
    if (!s2) {
        cudaStreamCreateWithFlags(&s2, cudaStreamNonBlocking);
        cudaEventCreateWithFlags(&evFork, cudaEventDisableTiming);
        cudaEventCreateWithFlags(&evJoin, cudaEventDisableTiming);
    }

    void *p_h, *p_zA, *p_zB;
    void *p_st1, *p_sc1, *p_sh1, *p_st2, *p_sc2, *p_sh2, *p_pool, *p_cnt;
    void *p_c0, *p_c1, *p_K, *p_W1, *p_b1, *p_W2, *p_b2;
    cudaGetSymbolAddress(&p_h,   g_h);
    cudaGetSymbolAddress(&p_zA,  g_zA);
    cudaGetSymbolAddress(&p_zB,  g_zB);
    cudaGetSymbolAddress(&p_st1, g_stats1);
    cudaGetSymbolAddress(&p_sc1, g_scale1);
    cudaGetSymbolAddress(&p_sh1, g_shift1);
    cudaGetSymbolAddress(&p_st2, g_stats2);
    cudaGetSymbolAddress(&p_sc2, g_scale2);
    cudaGetSymbolAddress(&p_sh2, g_shift2);
    cudaGetSymbolAddress(&p_pool, g_pooled);
    cudaGetSymbolAddress(&p_cnt,  g_counts);
    cudaGetSymbolAddress(&p_c0,   g_cnt0);
    cudaGetSymbolAddress(&p_c1,   g_cnt1);
    cudaGetSymbolAddress(&p_K,    g_K);
    cudaGetSymbolAddress(&p_W1,   g_W1);
    cudaGetSymbolAddress(&p_b1,   g_b1);
    cudaGetSymbolAddress(&p_W2,   g_W2);
    cudaGetSymbolAddress(&p_b2,   g_b2);

    cudaMemsetAsync(p_c0,  0, N * sizeof(int));
    cudaMemsetAsync(p_c1,  0, NHE * sizeof(int));
    cudaMemsetAsync(p_st1, 0, 2 * CDIM * sizeof(float));
    cudaMemsetAsync(p_st2, 0, 2 * HDIM * sizeof(float));
    cudaMemsetAsync(p_pool, 0, GNUM * HDIM * sizeof(float));
    cudaMemsetAsync(p_cnt,  0, GNUM * sizeof(float));
    cudaMemsetAsync(p_K,    0, 93 * 48 * sizeof(float));

    // ---- fork: CSR + S + K chain on s2 (needs only raw inputs) ----
    cudaEventRecord(evFork, 0);
    cudaStreamWaitEvent(s2, evFork, 0);

    const dim3 t256(256);
    count_edges  <<<1184, t256, 0, s2>>>(idx0, idx1, E);
    scan_counts  <<<1, 1024, 0, s2>>>(N);
    scatter_edges<<<1184, t256, 0, s2>>>(idx0, idx1, E);
    shedge_gather<<<(N + 7) / 8, t256, 0, s2>>>(hedge, N);
    kgemm        <<<232, t256, 0, s2>>>(x, N);
    cudaEventRecord(evJoin, s2);

    // ---- main stream: weight prep + GEMMs ----
    w1prep<<<93, t256>>>(embed_w, embed_b, lin_w);
    w2prep<<<41, t256>>>(bembed_w, bembed_b, lin_w, lin_b);

    const int mbN   = (N   + 127) / 128;
    const int mbNHE = (NHE + 127) / 128;
    sgemm<<<dim3(mbN, 1),   t256>>>(x,     embed_w,       embed_b,       (float*)p_h,  N,   128, 92);
    sgemm<<<dim3(mbN, 2),   t256>>>(x,     (float*)p_W1,  (float*)p_b1,  (float*)p_zA, N,   256, 92);
    sgemm<<<dim3(mbNHE, 2), t256>>>(hedge, (float*)p_W2,  (float*)p_b2,  (float*)p_zB, NHE, 256, 40);

    // ---- join, then BN1 stats + finalize ----
    cudaStreamWaitEvent(0, evJoin, 0);
    weighted_stats<<<(N * 32 + 255) / 256,   t256>>>((float*)p_zA, (const int*)p_c0, N);
    weighted_stats<<<(NHE * 32 + 255) / 256, t256>>>((float*)p_zB, (const int*)p_c1, NHE);
    cross_add<<<93, t256>>>();
    bn_finalize<<<1, 256>>>((float*)p_st1, bn1_g, bn1_b, 1.0f / (float)E, 256,
                            (float*)p_sc1, (float*)p_sh1);

    // ---- message + softmax aggregation + BN2 ----
    node_aggregate<<<(N + 7) / 8, t256>>>(aggr_t, N);
    bn_finalize<<<1, 128>>>((float*)p_st2, bn2_g, bn2_b, 1.0f / (float)N, 128,
                            (float*)p_sc2, (float*)p_sh2);

    node_final<<<(N * 32 + 255) / 256, t256>>>(batch, N);
    head<<<GNUM, t256>>>(l1_w, l1_b, out_w, out_b, (float*)d_out);
}

// round 15
// speedup vs baseline: 1.3889x; 1.1300x over previous
#include <cuda_runtime.h>
#include <cstdint>

// ---------------- problem constants (shapes fixed by the dataset) ----------
#define NMAX   50000
#define EMAX   800000
#define HDIM   128
#define CDIM   256      // 2*H
#define GNUM   128

// ---------------- scratch (static device globals; no runtime allocation) --
__device__ __align__(16) float g_h     [NMAX * HDIM];     // node embeddings      [N,128]
__device__ __align__(16) float g_zA    [NMAX * CDIM];     // x @ W1 + b1          [N,256]
__device__ __align__(16) float g_zB    [NMAX * CDIM];     // hedge @ W2 + b2      [NHE,256]
__device__ __align__(16) float g_out   [NMAX * HDIM];     // aggregated msgs      [N,128]
__device__ __align__(16) float g_W1f   [92 * 384];        // fused [W1 | embed_w]
__device__ __align__(16) float g_b1f   [384];             // fused [b1 | embed_b]
__device__ __align__(16) float g_W2    [40 * CDIM];       // bembed_w @ Wb
__device__ __align__(16) float g_b2    [CDIM];
__device__ __align__(16) float g_S     [NMAX * 48];       // per-node seg-sum of hedge rows [N,48]
__device__ __align__(16) float g_K     [93 * 48];         // x^e^T @ S  [93,41] padded
__device__ __align__(16) float g_stats1[2 * CDIM];        // BN1 sum / sumsq
__device__ __align__(16) float g_scale1[CDIM];
__device__ __align__(16) float g_shift1[CDIM];
__device__ __align__(16) float g_stats2[2 * HDIM];        // BN2 sum / sumsq
__device__ __align__(16) float g_scale2[HDIM];
__device__ __align__(16) float g_shift2[HDIM];
__device__ __align__(16) float g_pooled[GNUM * HDIM];
__device__ __align__(16) float g_counts[GNUM];
// CSR scratch
__device__ int g_cnt0  [NMAX];
__device__ int g_cnt1  [NMAX];
__device__ int g_base  [NMAX];
__device__ int g_cursor[NMAX];
__device__ int g_ei1   [EMAX];

// ---------------- helpers --------------------------------------------------
static __device__ __forceinline__ float softplusf_fast(float x) {
    return fmaxf(x, 0.f) + __logf(1.f + __expf(-fabsf(x)));
}
static __device__ __forceinline__ float sigmoidf_fast(float x) {
    return __fdividef(1.f, 1.f + __expf(-x));
}
static __device__ __forceinline__ void red_add_v4(float* p, float a, float b, float c, float d) {
    asm volatile("red.global.add.v4.f32 [%0], {%1, %2, %3, %4};"
                 :: "l"(p), "f"(a), "f"(b), "f"(c), "f"(d) : "memory");
}
static __device__ __forceinline__ uint32_t f2tf32(float x) {
    uint32_t r;
    asm("cvt.rna.tf32.f32 %0, %1;" : "=r"(r) : "f"(x));
    return r;
}
static __device__ __forceinline__ void mma_tf32(float* d, const uint32_t* a, const uint32_t* b) {
    asm volatile(
        "mma.sync.aligned.m16n8k8.row.col.f32.tf32.tf32.f32 "
        "{%0,%1,%2,%3}, {%4,%5,%6,%7}, {%8,%9}, {%0,%1,%2,%3};"
        : "+f"(d[0]), "+f"(d[1]), "+f"(d[2]), "+f"(d[3])
        : "r"(a[0]), "r"(a[1]), "r"(a[2]), "r"(a[3]), "r"(b[0]), "r"(b[1]));
}

// ---------------- tf32 tensor-core GEMM (3xTF32 accuracy) ------------------
// C[M,N] = A[M,K] @ B[K,N] + bias.  Block tile 128x128, 8 warps (4m x 2n),
// warp tile 32x64.  Output split: cols < splitN -> C0 (ldc0), else C1 (ldc1).
__global__ void __launch_bounds__(256) tgemm(
    const float* __restrict__ A, const float* __restrict__ B,
    const float* __restrict__ bias,
    float* __restrict__ C0, int ldc0,
    float* __restrict__ C1, int ldc1, int splitN,
    int M, int N, int K, int lda, int ldb)
{
    __shared__ float sAhi[128][20], sAlo[128][20];   // [m][k], stride 20 (bank-clean)
    __shared__ float sBhi[16][136], sBlo[16][136];   // [k][n], stride 136 (bank-clean)

    const int tid   = threadIdx.x;
    const int lane  = tid & 31;
    const int wid   = tid >> 5;
    const int warpM = wid & 3;          // 0..3  -> 32-row slab
    const int warpN = wid >> 2;         // 0..1  -> 64-col slab
    const int g     = lane >> 2;        // groupID
    const int t     = lane & 3;         // thread-in-group
    const int m0    = blockIdx.x * 128;
    const int n0    = blockIdx.y * 128;

    float cacc[2][8][4];
    #pragma unroll
    for (int mi = 0; mi < 2; mi++)
        #pragma unroll
        for (int nj = 0; nj < 8; nj++)
            #pragma unroll
            for (int q = 0; q < 4; q++) cacc[mi][nj][q] = 0.f;

    // load mappings
    const int ar  = tid >> 1;           // A row 0..127
    const int akq = (tid & 1) * 8;      // A k offset 0/8
    const int bkr = tid >> 4;           // B k row 0..15
    const int bnq = (tid & 15) * 8;     // B n offset

    for (int k0 = 0; k0 < K; k0 += 16) {
        // ---- A tile (scalar loads; lda not 16B-aligned in general) ----
        {
            const int row = m0 + ar;
            const bool rok = row < M;
            #pragma unroll
            for (int i = 0; i < 8; i++) {
                const int kk = k0 + akq + i;
                float v = (rok && kk < K) ? A[(size_t)row * lda + kk] : 0.f;
                float hf = __uint_as_float(f2tf32(v));
                sAhi[ar][akq + i] = hf;
                sAlo[ar][akq + i] = __uint_as_float(f2tf32(v - hf));
            }
        }
        // ---- B tile ----
        {
            const int kk = k0 + bkr;
            if (kk < K) {
                const float* bp = B + (size_t)kk * ldb + n0 + bnq;
                float4 v0 = *(const float4*)bp;
                float4 v1 = *(const float4*)(bp + 4);
                float vv[8] = {v0.x, v0.y, v0.z, v0.w, v1.x, v1.y, v1.z, v1.w};
                #pragma unroll
                for (int i = 0; i < 8; i++) {
                    float hf = __uint_as_float(f2tf32(vv[i]));
                    sBhi[bkr][bnq + i] = hf;
                    sBlo[bkr][bnq + i] = __uint_as_float(f2tf32(vv[i] - hf));
                }
            } else {
                #pragma unroll
                for (int i = 0; i < 8; i++) {
                    sBhi[bkr][bnq + i] = 0.f;
                    sBlo[bkr][bnq + i] = 0.f;
                }
            }
        }
        __syncthreads();

        #pragma unroll
        for (int ks = 0; ks < 16; ks += 8) {
            uint32_t ah[2][4], al[2][4];
            #pragma unroll
            for (int mi = 0; mi < 2; mi++) {
                const int r0 = warpM * 32 + mi * 16;
                ah[mi][0] = __float_as_uint(sAhi[r0 + g    ][ks + t    ]);
                ah[mi][1] = __float_as_uint(sAhi[r0 + g + 8][ks + t    ]);
                ah[mi][2] = __float_as_uint(sAhi[r0 + g    ][ks + t + 4]);
                ah[mi][3] = __float_as_uint(sAhi[r0 + g + 8][ks + t + 4]);
                al[mi][0] = __float_as_uint(sAlo[r0 + g    ][ks + t    ]);
                al[mi][1] = __float_as_uint(sAlo[r0 + g + 8][ks + t    ]);
                al[mi][2] = __float_as_uint(sAlo[r0 + g    ][ks + t + 4]);
                al[mi][3] = __float_as_uint(sAlo[r0 + g + 8][ks + t + 4]);
            }
            #pragma unroll
            for (int nj = 0; nj < 8; nj++) {
                const int cb = warpN * 64 + nj * 8 + g;
                uint32_t bh[2], bl[2];
                bh[0] = __float_as_uint(sBhi[ks + t    ][cb]);
                bh[1] = __float_as_uint(sBhi[ks + t + 4][cb]);
                bl[0] = __float_as_uint(sBlo[ks + t    ][cb]);
                bl[1] = __float_as_uint(sBlo[ks + t + 4][cb]);
                #pragma unroll
                for (int mi = 0; mi < 2; mi++) {
                    mma_tf32(cacc[mi][nj], ah[mi], bh);   // hi*hi
                    mma_tf32(cacc[mi][nj], ah[mi], bl);   // hi*lo
                    mma_tf32(cacc[mi][nj], al[mi], bh);   // lo*hi
                }
            }
        }
        __syncthreads();
    }

    // ---- epilogue: bias + split store ----
    #pragma unroll
    for (int mi = 0; mi < 2; mi++) {
        #pragma unroll
        for (int half = 0; half < 2; half++) {
            const int row = m0 + warpM * 32 + mi * 16 + g + half * 8;
            if (row >= M) continue;
            #pragma unroll
            for (int nj = 0; nj < 8; nj++) {
                const int coln = n0 + warpN * 64 + nj * 8 + 2 * t;
                float2 v;
                v.x = cacc[mi][nj][half * 2 + 0] + bias[coln];
                v.y = cacc[mi][nj][half * 2 + 1] + bias[coln + 1];
                float* dst = (coln < splitN)
                           ? C0 + (size_t)row * ldc0 + coln
                           : C1 + (size_t)row * ldc1 + (coln - splitN);
                *(float2*)dst = v;
            }
        }
    }
}

// ---------------- weight prep ----------------------------------------------
// fused: cols 0..255 = embed_w@(Wa+Wc) (bias b1), cols 256..383 = embed_w (bias embed_b)
__global__ void __launch_bounds__(384) w1prep_fused(
    const float* __restrict__ embed_w, const float* __restrict__ embed_b,
    const float* __restrict__ lin_w)
{
    const int i = blockIdx.x;       // 0..92 (row 92 = bias)
    const int c = threadIdx.x;      // 0..383
    float acc;
    if (c < 256) {
        acc = 0.f;
        #pragma unroll 4
        for (int j = 0; j < 128; j++) {
            float we = (i < 92) ? embed_w[i * 128 + j] : embed_b[j];
            acc += we * (lin_w[j * 256 + c] + lin_w[(256 + j) * 256 + c]);
        }
    } else {
        acc = (i < 92) ? embed_w[i * 128 + (c - 256)] : embed_b[c - 256];
    }
    if (i < 92) g_W1f[i * 384 + c] = acc; else g_b1f[c] = acc;
}

__global__ void __launch_bounds__(256) w2prep(
    const float* __restrict__ bembed_w, const float* __restrict__ bembed_b,
    const float* __restrict__ lin_w, const float* __restrict__ lin_b)
{
    const int i = blockIdx.x;       // 0..40
    const int c = threadIdx.x;
    float acc = (i == 40) ? lin_b[c] : 0.f;
    #pragma unroll 4
    for (int j = 0; j < 128; j++) {
        float bw = (i < 40) ? bembed_w[i * 128 + j] : bembed_b[j];
        acc += bw * lin_w[(128 + j) * 256 + c];
    }
    if (i < 40) g_W2[i * 256 + c] = acc; else g_b2[c] = acc;
}

// ---------------- CSR build ------------------------------------------------
__global__ void __launch_bounds__(256) count_edges(
    const int* __restrict__ idx0, const int* __restrict__ idx1, int E)
{
    for (int e = blockIdx.x * 256 + threadIdx.x; e < E; e += gridDim.x * 256) {
        atomicAdd(&g_cnt0[idx0[e]], 1);
        atomicAdd(&g_cnt1[idx1[e]], 1);
    }
}

__global__ void __launch_bounds__(1024) scan_counts(int N)
{
    __shared__ int sh[1024];
    const int tid   = threadIdx.x;
    const int chunk = (N + 1023) / 1024;
    const int start = tid * chunk;
    const int end   = min(start + chunk, N);

    int s = 0;
    for (int i = start; i < end; i++) s += g_cnt0[i];
    sh[tid] = s;
    __syncthreads();
    for (int off = 1; off < 1024; off <<= 1) {
        int v = (tid >= off) ? sh[tid - off] : 0;
        __syncthreads();
        sh[tid] += v;
        __syncthreads();
    }
    int run = sh[tid] - s;
    for (int i = start; i < end; i++) {
        int c = g_cnt0[i];
        g_base[i]   = run;
        g_cursor[i] = run;
        run += c;
    }
}

__global__ void __launch_bounds__(256) scatter_edges(
    const int* __restrict__ idx0, const int* __restrict__ idx1, int E)
{
    for (int e = blockIdx.x * 256 + threadIdx.x; e < E; e += gridDim.x * 256) {
        int p = atomicAdd(&g_cursor[idx0[e]], 1);
        g_ei1[p] = idx1[e];
    }
}

// ---------------- S[n] = seg-sum of hedge rows over node n's edges ---------
__global__ void __launch_bounds__(256) shedge_gather(
    const float* __restrict__ hedge, int N)
{
    const int tid  = threadIdx.x;
    const int lane = tid & 31;
    const int n    = blockIdx.x * 8 + (tid >> 5);
    if (n >= N) return;

    const int base = g_base[n];
    const int cnt  = g_cnt0[n];
    float lo = 0.f, hi = 0.f;
    int k = 0;
    for (; k + 2 <= cnt; k += 2) {
        int m0 = g_ei1[base + k];
        int m1 = g_ei1[base + k + 1];
        const float* h0 = hedge + (size_t)m0 * 40;
        const float* h1 = hedge + (size_t)m1 * 40;
        lo += h0[lane] + h1[lane];
        if (lane < 8) hi += h0[32 + lane] + h1[32 + lane];
    }
    if (k < cnt) {
        const float* h0 = hedge + (size_t)g_ei1[base + k] * 40;
        lo += h0[lane];
        if (lane < 8) hi += h0[32 + lane];
    }
    g_S[(size_t)n * 48 + lane] = lo;
    if (lane < 8)  g_S[(size_t)n * 48 + 32 + lane] = hi;
    if (lane == 0) g_S[(size_t)n * 48 + 40] = (float)cnt;
}

// ---------------- K[93,41] = x^e^T @ S -------------------------------------
__global__ void __launch_bounds__(256) kgemm(const float* __restrict__ x, int N)
{
    __shared__ __align__(16) float sx[64][96];
    __shared__ __align__(16) float sS[64][48];
    const int tid = threadIdx.x;

    int task[4], ti[4], tj[4];
    float4 acc[4];
    #pragma unroll
    for (int t = 0; t < 4; t++) {
        task[t] = tid + t * 256;
        ti[t] = task[t] / 11;
        tj[t] = (task[t] % 11) * 4;
        acc[t] = make_float4(0.f, 0.f, 0.f, 0.f);
    }

    for (int n0 = blockIdx.x * 64; n0 < N; n0 += gridDim.x * 64) {
        for (int idx = tid; idx < 64 * 92; idx += 256) {
            int r = idx / 92, c = idx % 92;
            int n = n0 + r;
            sx[r][c] = (n < N) ? x[(size_t)n * 92 + c] : 0.f;
        }
        if (tid < 64) sx[tid][92] = (n0 + tid < N) ? 1.f : 0.f;
        for (int idx = tid; idx < 64 * 48; idx += 256) {
            int r = idx / 48, c = idx % 48;
            int n = n0 + r;
            sS[r][c] = (n < N) ? g_S[(size_t)n * 48 + c] : 0.f;
        }
        __syncthreads();

        for (int r = 0; r < 64; r++) {
            #pragma unroll
            for (int t = 0; t < 4; t++) {
                if (task[t] < 1023) {
                    float a = sx[r][ti[t]];
                    float4 v = *(const float4*)&sS[r][tj[t]];
                    acc[t].x += a * v.x; acc[t].y += a * v.y;
                    acc[t].z += a * v.z; acc[t].w += a * v.w;
                }
            }
        }
        __syncthreads();
    }

    #pragma unroll
    for (int t = 0; t < 4; t++) {
        if (task[t] < 1023) {
            float* kp = &g_K[ti[t] * 48 + tj[t]];
            atomicAdd(kp + 0, acc[t].x);
            atomicAdd(kp + 1, acc[t].y);
            atomicAdd(kp + 2, acc[t].z);
            atomicAdd(kp + 3, acc[t].w);
        }
    }
}

// ---------------- cross term: stats1[256+c] += 2 * W1e[:,c]^T K W2e[:,c] ---
__global__ void __launch_bounds__(256) cross_add()
{
    __shared__ float kr[48];
    const int i = blockIdx.x;      // 0..92
    const int c = threadIdx.x;
    if (c < 48) kr[c] = g_K[i * 48 + c];
    __syncthreads();

    float inner = g_b2[c] * kr[40];
    #pragma unroll 4
    for (int j = 0; j < 40; j++)
        inner += kr[j] * g_W2[j * 256 + c];
    float w1 = (i < 92) ? g_W1f[i * 384 + c] : g_b1f[c];
    atomicAdd(&g_stats1[256 + c], 2.f * w1 * inner);
}

// ---------------- degree-weighted self sums into BN1 stats -----------------
__global__ void __launch_bounds__(256) weighted_stats(
    const float* __restrict__ Z, const int* __restrict__ cnt, int R)
{
    __shared__ float ss[512];
    const int tid = threadIdx.x;
    for (int i = tid; i < 512; i += 256) ss[i] = 0.f;
    __syncthreads();

    const int gid = blockIdx.x * 256 + tid;
    const int r = gid >> 5;
    const int g = gid & 31;
    if (r < R) {
        const float w = (float)cnt[r];
        if (w > 0.f) {
            const float4* Z4 = (const float4*)Z;
            float4 z0 = Z4[(size_t)r * 64 + g];
            float4 z1 = Z4[(size_t)r * 64 + 32 + g];
            const int c = 4 * g;
            atomicAdd(&ss[c + 0], w * z0.x); atomicAdd(&ss[c + 1], w * z0.y);
            atomicAdd(&ss[c + 2], w * z0.z); atomicAdd(&ss[c + 3], w * z0.w);
            atomicAdd(&ss[128 + c + 0], w * z1.x); atomicAdd(&ss[128 + c + 1], w * z1.y);
            atomicAdd(&ss[128 + c + 2], w * z1.z); atomicAdd(&ss[128 + c + 3], w * z1.w);
            atomicAdd(&ss[256 + c + 0], w * z0.x * z0.x); atomicAdd(&ss[256 + c + 1], w * z0.y * z0.y);
            atomicAdd(&ss[256 + c + 2], w * z0.z * z0.z); atomicAdd(&ss[256 + c + 3], w * z0.w * z0.w);
            atomicAdd(&ss[384 + c + 0], w * z1.x * z1.x); atomicAdd(&ss[384 + c + 1], w * z1.y * z1.y);
            atomicAdd(&ss[384 + c + 2], w * z1.z * z1.z); atomicAdd(&ss[384 + c + 3], w * z1.w * z1.w);
        }
    }
    __syncthreads();
    for (int i = tid; i < 512; i += 256)
        if (ss[i] != 0.f) atomicAdd(&g_stats1[i], ss[i]);
}

// ---------------- BN finalize ----------------------------------------------
__global__ void bn_finalize(const float* __restrict__ stats,
                            const float* __restrict__ gma,
                            const float* __restrict__ bta,
                            float inv, int C,
                            float* __restrict__ scale, float* __restrict__ shift)
{
    const int c = blockIdx.x * blockDim.x + threadIdx.x;
    if (c < C) {
        float mean = stats[c] * inv;
        float var  = fmaxf(stats[C + c] * inv - mean * mean, 0.f);
        float s    = gma[c] * rsqrtf(var + 1e-5f);
        scale[c] = s;
        shift[c] = bta[c] - mean * s;
    }
}

// ---------------- message + softmax aggregation (warp per node, CSR) -------
__global__ void __launch_bounds__(256) node_aggregate(
    const float* __restrict__ aggr_t, int N)
{
    __shared__ float ss[256];
    const int tid = threadIdx.x;
    ss[tid] = 0.f;
    __syncthreads();

    const int lane = tid & 31;
    const int n = blockIdx.x * 8 + (tid >> 5);
    if (n < N) {
        const float4* zA4 = (const float4*)g_zA;
        const float4* zB4 = (const float4*)g_zB;
        const float4 sf = *(const float4*)&g_scale1[4 * lane];
        const float4 tf = *(const float4*)&g_shift1[4 * lane];
        const float4 sc = *(const float4*)&g_scale1[128 + 4 * lane];
        const float4 tc = *(const float4*)&g_shift1[128 + 4 * lane];
        const float  T  = *aggr_t;

        float4 a0 = zA4[(size_t)n * 64 + lane];
        float4 a1 = zA4[(size_t)n * 64 + 32 + lane];
        const float4 af = {a0.x * sf.x + tf.x, a0.y * sf.y + tf.y,
                           a0.z * sf.z + tf.z, a0.w * sf.w + tf.w};
        const float4 ac = {a1.x * sc.x + tc.x, a1.y * sc.y + tc.y,
                           a1.z * sc.z + tc.z, a1.w * sc.w + tc.w};

        const int base = g_base[n];
        const int cnt  = g_cnt0[n];

        float nx = 0, ny = 0, nz = 0, nw = 0;
        float dx = 0, dy = 0, dz = 0, dw = 0;

        #define PROC(mIdx)                                                    \
        {                                                                     \
            float4 b0 = zB4[(size_t)(mIdx) * 64 + lane];                      \
            float4 b1 = zB4[(size_t)(mIdx) * 64 + 32 + lane];                 \
            float mx = sigmoidf_fast(af.x + b0.x * sf.x) *                    \
                       softplusf_fast(ac.x + b1.x * sc.x);                    \
            float my = sigmoidf_fast(af.y + b0.y * sf.y) *                    \
                       softplusf_fast(ac.y + b1.y * sc.y);                    \
            float mz = sigmoidf_fast(af.z + b0.z * sf.z) *                    \
                       softplusf_fast(ac.z + b1.z * sc.z);                    \
            float mw = sigmoidf_fast(af.w + b0.w * sf.w) *                    \
                       softplusf_fast(ac.w + b1.w * sc.w);                    \
            float ex = __expf(T * mx); float ey = __expf(T * my);             \
            float ez = __expf(T * mz); float ew = __expf(T * mw);             \
            dx += ex; dy += ey; dz += ez; dw += ew;                           \
            nx += mx * ex; ny += my * ey; nz += mz * ez; nw += mw * ew;       \
        }

        int k = 0;
        for (; k + 2 <= cnt; k += 2) {
            int m0 = g_ei1[base + k];
            int m1 = g_ei1[base + k + 1];
            PROC(m0);
            PROC(m1);
        }
        if (k < cnt) {
            int m0 = g_ei1[base + k];
            PROC(m0);
        }
        #undef PROC

        float ox = nx / (dx + 1e-16f);
        float oy = ny / (dy + 1e-16f);
        float oz = nz / (dz + 1e-16f);
        float ow = nw / (dw + 1e-16f);

        ((float4*)g_out)[(size_t)n * 32 + lane] = make_float4(ox, oy, oz, ow);

        const int c = 4 * lane;
        atomicAdd(&ss[c + 0], ox); atomicAdd(&ss[c + 1], oy);
        atomicAdd(&ss[c + 2], oz); atomicAdd(&ss[c + 3], ow);
        atomicAdd(&ss[128 + c + 0], ox * ox); atomicAdd(&ss[128 + c + 1], oy * oy);
        atomicAdd(&ss[128 + c + 2], oz * oz); atomicAdd(&ss[128 + c + 3], ow * ow);
    }
    __syncthreads();
    if (ss[tid] != 0.f) atomicAdd(&g_stats2[tid], ss[tid]);
}

// ---------------- node final: h' = softplus(BN2(out)+h); pool + counts -----
__global__ void __launch_bounds__(256) node_final(
    const int* __restrict__ batch, int N)
{
    const int gid = blockIdx.x * 256 + threadIdx.x;
    const int n = gid >> 5;
    const int g = gid & 31;
    if (n >= N) return;

    float4 o  = ((const float4*)g_out)[(size_t)n * 32 + g];
    float4 s2 = *(const float4*)&g_scale2[4 * g];
    float4 t2 = *(const float4*)&g_shift2[4 * g];
    float4 hv = ((const float4*)g_h)[(size_t)n * 32 + g];

    float vx = softplusf_fast(o.x * s2.x + t2.x + hv.x);
    float vy = softplusf_fast(o.y * s2.y + t2.y + hv.y);
    float vz = softplusf_fast(o.z * s2.z + t2.z + hv.z);
    float vw = softplusf_fast(o.w * s2.w + t2.w + hv.w);

    const int b = batch[n];
    if (g == 0) atomicAdd(&g_counts[b], 1.f);
    red_add_v4(&g_pooled[(size_t)b * 128 + 4 * g], vx, vy, vz, vw);
}

// ---------------- head: mean pool -> softplus(MLP) -> linear ---------------
__global__ void __launch_bounds__(256) head(
    const float* __restrict__ l1_w, const float* __restrict__ l1_b,
    const float* __restrict__ out_w, const float* __restrict__ out_b,
    float* __restrict__ out)
{
    __shared__ float p[128];
    __shared__ float red[256];
    const int g = blockIdx.x;
    const int tid = threadIdx.x;
    if (tid < 128)
        p[tid] = g_pooled[g * 128 + tid] / fmaxf(g_counts[g], 1.f);
    __syncthreads();

    float acc = l1_b[tid];
    #pragma unroll 8
    for (int k = 0; k < 128; k++)
        acc += p[k] * l1_w[k * 256 + tid];
    red[tid] = softplusf_fast(acc) * out_w[tid];
    __syncthreads();
    for (int s = 128; s > 0; s >>= 1) {
        if (tid < s) red[tid] += red[tid + s];
        __syncthreads();
    }
    if (tid == 0) out[g] = red[0] + out_b[0];
}

// ---------------- launch ---------------------------------------------------
extern "C" void kernel_launch(void* const* d_in, const int* in_sizes, int n_in,
                              void* d_out, int out_size)
{
    const float* x        = (const float*)d_in[0];
    const float* hedge    = (const float*)d_in[1];
    const int*   rel      = (const int*)d_in[2];      // int32 (JAX x64 disabled)
    const int*   batch    = (const int*)d_in[3];      // int32
    const float* embed_w  = (const float*)d_in[5];
    const float* embed_b  = (const float*)d_in[6];
    const float* bembed_w = (const float*)d_in[7];
    const float* bembed_b = (const float*)d_in[8];
    const float* lin_w    = (const float*)d_in[9];
    const float* lin_b    = (const float*)d_in[10];
    const float* bn1_g    = (const float*)d_in[11];
    const float* bn1_b    = (const float*)d_in[12];
    const float* bn2_g    = (const float*)d_in[13];
    const float* bn2_b    = (const float*)d_in[14];
    const float* aggr_t   = (const float*)d_in[15];
    const float* l1_w     = (const float*)d_in[16];
    const float* l1_b     = (const float*)d_in[17];
    const float* out_w    = (const float*)d_in[18];
    const float* out_b    = (const float*)d_in[19];

    const int N   = in_sizes[0] / 92;
    const int NHE = in_sizes[1] / 40;
    const int E   = in_sizes[2] / 3;
    const int* idx0 = rel;
    const int* idx1 = rel + E;

    // side streams + events (created once; capture-legal)
    static cudaStream_t s2 = nullptr, s3 = nullptr;
    static cudaEvent_t evFork = nullptr, evJoin2 = nullptr, evJoin3 = nullptr;
    if (!s2) {
        cudaStreamCreateWithFlags(&s2, cudaStreamNonBlocking);
        cudaStreamCreateWithFlags(&s3, cudaStreamNonBlocking);
        cudaEventCreateWithFlags(&evFork,  cudaEventDisableTiming);
        cudaEventCreateWithFlags(&evJoin2, cudaEventDisableTiming);
        cudaEventCreateWithFlags(&evJoin3, cudaEventDisableTiming);
    }

    void *p_h, *p_zA, *p_zB;
    void *p_st1, *p_sc1, *p_sh1, *p_st2, *p_sc2, *p_sh2, *p_pool, *p_cnt;
    void *p_c0, *p_c1, *p_K, *p_W1f, *p_b1f, *p_W2, *p_b2;
    cudaGetSymbolAddress(&p_h,   g_h);
    cudaGetSymbolAddress(&p_zA,  g_zA);
    cudaGetSymbolAddress(&p_zB,  g_zB);
    cudaGetSymbolAddress(&p_st1, g_stats1);
    cudaGetSymbolAddress(&p_sc1, g_scale1);
    cudaGetSymbolAddress(&p_sh1, g_shift1);
    cudaGetSymbolAddress(&p_st2, g_stats2);
    cudaGetSymbolAddress(&p_sc2, g_scale2);
    cudaGetSymbolAddress(&p_sh2, g_shift2);
    cudaGetSymbolAddress(&p_pool, g_pooled);
    cudaGetSymbolAddress(&p_cnt,  g_counts);
    cudaGetSymbolAddress(&p_c0,   g_cnt0);
    cudaGetSymbolAddress(&p_c1,   g_cnt1);
    cudaGetSymbolAddress(&p_K,    g_K);
    cudaGetSymbolAddress(&p_W1f,  g_W1f);
    cudaGetSymbolAddress(&p_b1f,  g_b1f);
    cudaGetSymbolAddress(&p_W2,   g_W2);
    cudaGetSymbolAddress(&p_b2,   g_b2);

    cudaMemsetAsync(p_c0,  0, N * sizeof(int));
    cudaMemsetAsync(p_c1,  0, NHE * sizeof(int));
    cudaMemsetAsync(p_st1, 0, 2 * CDIM * sizeof(float));
    cudaMemsetAsync(p_st2, 0, 2 * HDIM * sizeof(float));
    cudaMemsetAsync(p_pool, 0, GNUM * HDIM * sizeof(float));
    cudaMemsetAsync(p_cnt,  0, GNUM * sizeof(float));
    cudaMemsetAsync(p_K,    0, 93 * 48 * sizeof(float));

    cudaEventRecord(evFork, 0);
    cudaStreamWaitEvent(s2, evFork, 0);
    cudaStreamWaitEvent(s3, evFork, 0);

    const dim3 t256(256);

    // ---- s2: CSR + S + K chain (raw inputs only) ----
    count_edges  <<<1184, t256, 0, s2>>>(idx0, idx1, E);
    scan_counts  <<<1, 1024, 0, s2>>>(N);
    scatter_edges<<<1184, t256, 0, s2>>>(idx0, idx1, E);
    shedge_gather<<<(N + 7) / 8, t256, 0, s2>>>(hedge, N);
    kgemm        <<<232, t256, 0, s2>>>(x, N);
    cudaEventRecord(evJoin2, s2);

    // ---- s3: hedge-side weights + zB GEMM ----
    w2prep<<<41, t256, 0, s3>>>(bembed_w, bembed_b, lin_w, lin_b);
    tgemm<<<dim3((NHE + 127) / 128, 2), t256, 0, s3>>>(
        hedge, (const float*)p_W2, (const float*)p_b2,
        (float*)p_zB, 256, (float*)p_zB, 256, 1 << 30,
        NHE, 256, 40, 40, 256);
    cudaEventRecord(evJoin3, s3);

    // ---- main: fused node-side GEMM (zA cols 0..255, h cols 256..383) ----
    w1prep_fused<<<93, 384>>>(embed_w, embed_b, lin_w);
    tgemm<<<dim3((N + 127) / 128, 3), t256>>>(
        x, (const float*)p_W1f, (const float*)p_b1f,
        (float*)p_zA, 256, (float*)p_h, 128, 256,
        N, 384, 92, 92, 384);

    // ---- join, BN1 stats + finalize ----
    cudaStreamWaitEvent(0, evJoin2, 0);
    cudaStreamWaitEvent(0, evJoin3, 0);
    weighted_stats<<<(N * 32 + 255) / 256,   t256>>>((float*)p_zA, (const int*)p_c0, N);
    weighted_stats<<<(NHE * 32 + 255) / 256, t256>>>((float*)p_zB, (const int*)p_c1, NHE);
    cross_add<<<93, t256>>>();
    bn_finalize<<<1, 256>>>((float*)p_st1, bn1_g, bn1_b, 1.0f / (float)E, 256,
                            (float*)p_sc1, (float*)p_sh1);

    // ---- message + softmax aggregation + BN2 ----
    node_aggregate<<<(N + 7) / 8, t256>>>(aggr_t, N);
    bn_finalize<<<1, 128>>>((float*)p_st2, bn2_g, bn2_b, 1.0f / (float)N, 128,
                            (float*)p_sc2, (float*)p_sh2);

    node_final<<<(N * 32 + 255) / 256, t256>>>(batch, N);
    head<<<GNUM, t256>>>(l1_w, l1_b, out_w, out_b, (float*)d_out);
}